// round 10
// baseline (speedup 1.0000x reference)
#include <cuda_runtime.h>
#include <cuda_bf16.h>
#include <cstdint>

#define Bn 8
#define Sn 2048
#define En 1024
#define Hn 64
#define Mn (Bn * Sn)
#define QT_N 16
#define CHUNK 4
#define MAXC 8

__device__ uint32_t g_qh[Mn * 32];
__device__ uint32_t g_ql[Mn * 32];
__device__ uint32_t g_kh[Mn * 32];
__device__ uint32_t g_kl[Mn * 32];
__device__ uint32_t g_vth[Bn * Hn * (Sn / 2)];
__device__ uint32_t g_vtl[Bn * Hn * (Sn / 2)];

__device__ float g_po[(size_t)Bn * QT_N * MAXC * 128 * 64];
__device__ float g_pm[Bn * QT_N * MAXC * 128];
__device__ float g_pl[Bn * QT_N * MAXC * 128];
__device__ __nv_bfloat16 g_wt[6 * 64 * En];
__device__ __nv_bfloat16 g_xh[(size_t)Mn * En];
__device__ __nv_bfloat16 g_xl[(size_t)Mn * En];

__device__ __forceinline__ uint32_t smem_u32(const void* p) {
    uint32_t a;
    asm("{ .reg .u64 t; cvta.to.shared.u64 t, %1; cvt.u32.u64 %0, t; }" : "=r"(a) : "l"(p));
    return a;
}
__device__ __forceinline__ void mma16816(float* c, const uint32_t* a,
                                         uint32_t b0, uint32_t b1) {
    asm volatile(
        "mma.sync.aligned.m16n8k16.row.col.f32.bf16.bf16.f32 "
        "{%0,%1,%2,%3}, {%4,%5,%6,%7}, {%8,%9}, {%0,%1,%2,%3};"
        : "+f"(c[0]), "+f"(c[1]), "+f"(c[2]), "+f"(c[3])
        : "r"(a[0]), "r"(a[1]), "r"(a[2]), "r"(a[3]), "r"(b0), "r"(b1));
}
#define LDMX4(r, ad) \
    asm volatile("ldmatrix.sync.aligned.m8n8.x4.shared.b16 {%0,%1,%2,%3}, [%4];" \
        : "=r"((r)[0]), "=r"((r)[1]), "=r"((r)[2]), "=r"((r)[3]) : "r"(ad))

__device__ __forceinline__ uint32_t pack2bf(float f0, float f1) {
    __nv_bfloat16 b0 = __float2bfloat16(f0);
    __nv_bfloat16 b1 = __float2bfloat16(f1);
    return (uint32_t)__bfloat16_as_ushort(b0) | ((uint32_t)__bfloat16_as_ushort(b1) << 16);
}
__device__ __forceinline__ float lowf(uint32_t u)  { return __int_as_float(u << 16); }
__device__ __forceinline__ float highf(uint32_t u) { return __int_as_float(u & 0xFFFF0000u); }

__device__ __forceinline__ float fexp2(float arg) {
    arg = fmaxf(arg, -120.0f);
    float t = arg + 12582912.0f;
    int iv = __float_as_int(t) - 0x4B400000;
    float f = arg - (t - 12582912.0f);
    float p = 0.00133335581f;
    p = fmaf(p, f, 0.00961804886f);
    p = fmaf(p, f, 0.0555041086f);
    p = fmaf(p, f, 0.240226506f);
    p = fmaf(p, f, 0.693147180f);
    p = fmaf(p, f, 1.0f);
    return __int_as_float(__float_as_int(p) + (iv << 23));
}
#define C2 0.1803368801111204f

// ------------------- conv_w -------------------
__global__ __launch_bounds__(256) void conv_w_kernel(
    const float* __restrict__ wq, const float* __restrict__ wk, const float* __restrict__ wv)
{
    const float* wsrc[3] = {wq, wk, wv};
    int id = blockIdx.x * 256 + threadIdx.x;
    if (id >= 3 * Hn * En) return;
    int mat = id / (Hn * En);
    int rem = id % (Hn * En);
    int n = rem / En, k = rem % En;
    float v = wsrc[mat][(size_t)k * Hn + n];
    __nv_bfloat16 hi = __float2bfloat16(v);
    __nv_bfloat16 lo = __float2bfloat16(v - __bfloat162float(hi));
    g_wt[((size_t)(mat * 2 + 0) * Hn + n) * En + k] = hi;
    g_wt[((size_t)(mat * 2 + 1) * Hn + n) * En + k] = lo;
}

// ------------------- conv_x: fp32 -> bf16 hi/lo (DRAM-bound) -------------------
__global__ __launch_bounds__(256) void conv_x_kernel(const float* __restrict__ x)
{
    size_t id = (size_t)blockIdx.x * 256 + threadIdx.x;   // over Mn*En/8
    const float* xp = x + id * 8;
    float4 a = *(const float4*)xp;
    float4 b = *(const float4*)(xp + 4);
    float f[8] = {a.x, a.y, a.z, a.w, b.x, b.y, b.z, b.w};
    uint32_t hi[4], lo[4];
#pragma unroll
    for (int j = 0; j < 4; j++) {
        hi[j] = pack2bf(f[2*j], f[2*j+1]);
        lo[j] = pack2bf(f[2*j] - lowf(hi[j]), f[2*j+1] - highf(hi[j]));
    }
    ((uint4*)g_xh)[id] = make_uint4(hi[0], hi[1], hi[2], hi[3]);
    ((uint4*)g_xl)[id] = make_uint4(lo[0], lo[1], lo[2], lo[3]);
}

// ------------------- qkv: per-matrix blocks, pure-copy staging -------------------
#define KC 32
#define ALD 40
__global__ __launch_bounds__(128) void qkv_mma_kernel(
    const float* __restrict__ bq, const float* __restrict__ bk, const float* __restrict__ bv)
{
    __shared__ char qsm[20480];
    __nv_bfloat16* sAh = (__nv_bfloat16*)qsm;              // [64][40]
    __nv_bfloat16* sAl = (__nv_bfloat16*)(qsm + 5120);
    __nv_bfloat16* sBh = (__nv_bfloat16*)(qsm + 10240);
    __nv_bfloat16* sBl = (__nv_bfloat16*)(qsm + 15360);
    const int t = threadIdx.x, w = t >> 5, lane = t & 31;
    const int g = lane >> 2, tt = lane & 3;
    const int mat = blockIdx.x;
    const int m0  = blockIdx.y * 64;

    float acc[8][4];
#pragma unroll
    for (int n = 0; n < 8; n++)
#pragma unroll
        for (int i = 0; i < 4; i++) acc[n][i] = 0.0f;

    const int arow = w * 16 + (lane & 15);
    const int acol = (lane >> 4) << 3;
    const int brow = lane & 7;
    const int bcol = ((lane >> 3) & 3) << 3;

    // staging indices: 256 uint4 per array; thread does 2 rows-chunks per array
    const int sr = t >> 2, sc = t & 3;                    // row, uint4-col (8 bf16)

    for (int c = 0; c < En / KC; c++) {
        const int k0 = c * KC;
        __syncthreads();
#pragma unroll
        for (int i = 0; i < 2; i++) {
            int r = sr + i * 32;
            uint32_t eo = (uint32_t)(r * ALD + sc * 8);
            *(uint4*)&sAh[eo] = *(const uint4*)(g_xh + (size_t)(m0 + r) * En + k0 + sc * 8);
            *(uint4*)&sAl[eo] = *(const uint4*)(g_xl + (size_t)(m0 + r) * En + k0 + sc * 8);
            *(uint4*)&sBh[eo] = *(const uint4*)(g_wt + ((size_t)(mat*2+0)*64 + r) * En + k0 + sc * 8);
            *(uint4*)&sBl[eo] = *(const uint4*)(g_wt + ((size_t)(mat*2+1)*64 + r) * En + k0 + sc * 8);
        }
        __syncthreads();

        uint32_t aH[2][4], aL[2][4];
#pragma unroll
        for (int ks = 0; ks < 2; ks++) {
            LDMX4(aH[ks], smem_u32(&sAh[arow * ALD + ks * 16 + acol]));
            LDMX4(aL[ks], smem_u32(&sAl[arow * ALD + ks * 16 + acol]));
        }
#pragma unroll
        for (int n8 = 0; n8 < 8; n8++) {
            uint32_t bh[4], bl[4];
            LDMX4(bh, smem_u32(&sBh[(n8*8 + brow) * ALD + bcol]));
            LDMX4(bl, smem_u32(&sBl[(n8*8 + brow) * ALD + bcol]));
            mma16816(acc[n8], aH[0], bh[0], bh[1]);
            mma16816(acc[n8], aL[0], bh[0], bh[1]);
            mma16816(acc[n8], aH[0], bl[0], bl[1]);
            mma16816(acc[n8], aH[1], bh[2], bh[3]);
            mma16816(acc[n8], aL[1], bh[2], bh[3]);
            mma16816(acc[n8], aH[1], bl[2], bl[3]);
        }
    }

    const int rl = w * 16 + g;
    if (mat < 2) {
        uint32_t* gh = mat ? g_kh : g_qh;
        uint32_t* gl = mat ? g_kl : g_ql;
        const float* bp = mat ? bk : bq;
#pragma unroll
        for (int n8 = 0; n8 < 8; n8++) {
            int col = n8 * 8 + 2 * tt;
            float b0 = __ldg(bp + col), b1 = __ldg(bp + col + 1);
            float v00 = acc[n8][0] + b0, v01 = acc[n8][1] + b1;
            float v10 = acc[n8][2] + b0, v11 = acc[n8][3] + b1;
            uint32_t hA = pack2bf(v00, v01);
            uint32_t lA = pack2bf(v00 - lowf(hA), v01 - highf(hA));
            uint32_t hB = pack2bf(v10, v11);
            uint32_t lB = pack2bf(v10 - lowf(hB), v11 - highf(hB));
            size_t iA = (size_t)(m0 + rl) * 32 + n8 * 4 + tt;
            size_t iB = (size_t)(m0 + rl + 8) * 32 + n8 * 4 + tt;
            gh[iA] = hA; gl[iA] = lA;
            gh[iB] = hB; gl[iB] = lB;
        }
    } else {
        // V: transpose via smem (reuse whole qsm after sync)
        float* vsm = (float*)qsm;                // [64][66] = 16896 B
        __syncthreads();
#pragma unroll
        for (int n8 = 0; n8 < 8; n8++) {
            int col = n8 * 8 + 2 * tt;
            float b0 = __ldg(bv + col), b1 = __ldg(bv + col + 1);
            vsm[rl * 66 + col]           = acc[n8][0] + b0;
            vsm[rl * 66 + col + 1]       = acc[n8][1] + b1;
            vsm[(rl + 8) * 66 + col]     = acc[n8][2] + b0;
            vsm[(rl + 8) * 66 + col + 1] = acc[n8][3] + b1;
        }
        __syncthreads();
        int h = t >> 1, half = t & 1;
        int bb = m0 >> 11;
        int sp0 = ((m0 & 2047) + half * 32) >> 1;
        uint32_t oh[16], ol[16];
#pragma unroll
        for (int s = 0; s < 16; s++) {
            float a = vsm[(half * 32 + 2 * s) * 66 + h];
            float cc = vsm[(half * 32 + 2 * s + 1) * 66 + h];
            oh[s] = pack2bf(a, cc);
            ol[s] = pack2bf(a - lowf(oh[s]), cc - highf(oh[s]));
        }
        uint32_t* gvh = g_vth + (size_t)(bb * Hn + h) * (Sn / 2) + sp0;
        uint32_t* gvl = g_vtl + (size_t)(bb * Hn + h) * (Sn / 2) + sp0;
#pragma unroll
        for (int q = 0; q < 4; q++) {
            *(uint4*)(gvh + q * 4) = make_uint4(oh[q*4], oh[q*4+1], oh[q*4+2], oh[q*4+3]);
            *(uint4*)(gvl + q * 4) = make_uint4(ol[q*4], ol[q*4+1], ol[q*4+2], ol[q*4+3]);
        }
    }
}

// ------------------- attention partials (unchanged, passing) -------------------
#define AR64 2304
#define ARQ  4608
#define OFF_KH (2*ARQ)
#define OFF_KL (2*ARQ + AR64)
#define OFF_VH (2*ARQ + 2*AR64)
#define OFF_VL (2*ARQ + 3*AR64)
#define ATT_SMEM ((2*ARQ + 4*AR64) * 4)

__global__ __launch_bounds__(256) void attn_partial_kernel()
{
    const int chunk = blockIdx.x, qt = blockIdx.y, b = blockIdx.z;
    const int nt = 2 * qt + 2;
    const int jt0 = chunk * CHUNK;
    if (jt0 >= nt) return;
    const int jt1 = min(jt0 + CHUNK, nt);

    extern __shared__ uint32_t su[];
    const uint32_t sbase = smem_u32(su);
    const int t = threadIdx.x, w = t >> 5, lane = t & 31;
    const int g = lane >> 2, tt = lane & 3;
    const int qrow = w * 16 + g;

    const int arow = w * 16 + (lane & 15);
    const int acolB = ((lane >> 4) << 3) * 2;
    const int brow = lane & 7;
    const int bcolB = (((lane >> 3) & 3) << 3) * 2;

    {
        const uint4* qh4 = (const uint4*)g_qh;
        const uint4* ql4 = (const uint4*)g_ql;
        size_t gb = ((size_t)b * Sn + qt * 128) * 8;
#pragma unroll
        for (int i = 0; i < 4; i++) {
            int u = t + i * 256, r = u >> 3, c = u & 7;
            *(uint4*)&su[r * 36 + c * 4]       = qh4[gb + r * 8 + c];
            *(uint4*)&su[ARQ + r * 36 + c * 4] = ql4[gb + r * 8 + c];
        }
    }
    __syncthreads();

    uint32_t aQh[4][4], aQl[4][4];
#pragma unroll
    for (int ks = 0; ks < 4; ks++) {
        uint32_t ad = sbase + arow * 144 + ks * 32 + acolB;
        LDMX4(aQh[ks], ad);
        LDMX4(aQl[ks], ad + ARQ * 4);
    }

    float m0r = -1e30f, m1r = -1e30f, l0r = 0.0f, l1r = 0.0f;
    float O[8][4];
#pragma unroll
    for (int j = 0; j < 8; j++)
#pragma unroll
        for (int i = 0; i < 4; i++) O[j][i] = 0.0f;

    for (int jt = jt0; jt < jt1; jt++) {
        __syncthreads();
        {
            const uint4* kh4 = (const uint4*)g_kh;
            const uint4* kl4 = (const uint4*)g_kl;
            const uint4* vh4 = (const uint4*)g_vth;
            const uint4* vl4 = (const uint4*)g_vtl;
            size_t kb = ((size_t)b * Sn + jt * 64) * 8;
#pragma unroll
            for (int i = 0; i < 2; i++) {
                int u = t + i * 256, r = u >> 3, c = u & 7;
                *(uint4*)&su[OFF_KH + r * 36 + c * 4] = kh4[kb + r * 8 + c];
                *(uint4*)&su[OFF_KL + r * 36 + c * 4] = kl4[kb + r * 8 + c];
                size_t vb = (size_t)(b * Hn + r) * 256 + jt * 8 + c;
                *(uint4*)&su[OFF_VH + r * 36 + c * 4] = vh4[vb];
                *(uint4*)&su[OFF_VL + r * 36 + c * 4] = vl4[vb];
            }
        }
        __syncthreads();

        float S[8][4];
#pragma unroll
        for (int j = 0; j < 8; j++)
#pragma unroll
            for (int i = 0; i < 4; i++) S[j][i] = 0.0f;
#pragma unroll
        for (int j = 0; j < 8; j++) {
            uint32_t adh = sbase + (OFF_KH + (j * 8 + brow) * 36) * 4 + bcolB;
            uint32_t adl = sbase + (OFF_KL + (j * 8 + brow) * 36) * 4 + bcolB;
            uint32_t kh[4], kl[4], kh2[4], kl2[4];
            LDMX4(kh, adh);
            LDMX4(kl, adl);
            LDMX4(kh2, adh + 64);
            LDMX4(kl2, adl + 64);
            mma16816(S[j], aQh[0], kh[0], kh[1]);
            mma16816(S[j], aQl[0], kh[0], kh[1]);
            mma16816(S[j], aQh[0], kl[0], kl[1]);
            mma16816(S[j], aQh[1], kh[2], kh[3]);
            mma16816(S[j], aQl[1], kh[2], kh[3]);
            mma16816(S[j], aQh[1], kl[2], kl[3]);
            mma16816(S[j], aQh[2], kh2[0], kh2[1]);
            mma16816(S[j], aQl[2], kh2[0], kh2[1]);
            mma16816(S[j], aQh[2], kl2[0], kl2[1]);
            mma16816(S[j], aQh[3], kh2[2], kh2[3]);
            mma16816(S[j], aQl[3], kh2[2], kh2[3]);
            mma16816(S[j], aQh[3], kl2[2], kl2[3]);
        }

        if (jt >= 2 * qt) {
            int qg0 = qt * 128 + qrow, qg1 = qg0 + 8;
            int kbse = jt * 64;
#pragma unroll
            for (int j = 0; j < 8; j++) {
                int kc = kbse + j * 8 + 2 * tt;
                if (kc     > qg0) S[j][0] = -1e30f;
                if (kc + 1 > qg0) S[j][1] = -1e30f;
                if (kc     > qg1) S[j][2] = -1e30f;
                if (kc + 1 > qg1) S[j][3] = -1e30f;
            }
        }

        float mx0 = -1e30f, mx1 = -1e30f;
#pragma unroll
        for (int j = 0; j < 8; j++) {
            mx0 = fmaxf(mx0, fmaxf(S[j][0], S[j][1]));
            mx1 = fmaxf(mx1, fmaxf(S[j][2], S[j][3]));
        }
        mx0 = fmaxf(mx0, __shfl_xor_sync(0xffffffff, mx0, 1));
        mx0 = fmaxf(mx0, __shfl_xor_sync(0xffffffff, mx0, 2));
        mx1 = fmaxf(mx1, __shfl_xor_sync(0xffffffff, mx1, 1));
        mx1 = fmaxf(mx1, __shfl_xor_sync(0xffffffff, mx1, 2));
        float mn0 = fmaxf(m0r, mx0), mn1 = fmaxf(m1r, mx1);
        float al0 = fexp2((m0r - mn0) * C2), al1 = fexp2((m1r - mn1) * C2);
        l0r *= al0; l1r *= al1;
#pragma unroll
        for (int j = 0; j < 8; j++) {
            O[j][0] *= al0; O[j][1] *= al0; O[j][2] *= al1; O[j][3] *= al1;
        }

        uint32_t ph[4][4], pl[4][4];
        float s0 = 0.0f, s1 = 0.0f;
#pragma unroll
        for (int j = 0; j < 8; j++) {
            float p0 = fexp2((S[j][0] - mn0) * C2);
            float p1 = fexp2((S[j][1] - mn0) * C2);
            float p2 = fexp2((S[j][2] - mn1) * C2);
            float p3 = fexp2((S[j][3] - mn1) * C2);
            s0 += p0 + p1; s1 += p2 + p3;
            uint32_t h01 = pack2bf(p0, p1);
            uint32_t l01 = pack2bf(p0 - lowf(h01), p1 - highf(h01));
            uint32_t h23 = pack2bf(p2, p3);
            uint32_t l23 = pack2bf(p2 - lowf(h23), p3 - highf(h23));
            int s = j >> 1;
            if (!(j & 1)) { ph[s][0] = h01; ph[s][1] = h23; pl[s][0] = l01; pl[s][1] = l23; }
            else          { ph[s][2] = h01; ph[s][3] = h23; pl[s][2] = l01; pl[s][3] = l23; }
        }
        s0 += __shfl_xor_sync(0xffffffff, s0, 1);
        s0 += __shfl_xor_sync(0xffffffff, s0, 2);
        s1 += __shfl_xor_sync(0xffffffff, s1, 1);
        s1 += __shfl_xor_sync(0xffffffff, s1, 2);
        l0r += s0; l1r += s1;
        m0r = mn0; m1r = mn1;

#pragma unroll
        for (int j = 0; j < 8; j++) {
            uint32_t adh = sbase + (OFF_VH + (j * 8 + brow) * 36) * 4 + bcolB;
            uint32_t adl = sbase + (OFF_VL + (j * 8 + brow) * 36) * 4 + bcolB;
            uint32_t vh[4], vl[4], vh2[4], vl2[4];
            LDMX4(vh, adh);
            LDMX4(vl, adl);
            LDMX4(vh2, adh + 64);
            LDMX4(vl2, adl + 64);
            mma16816(O[j], ph[0], vh[0], vh[1]);
            mma16816(O[j], pl[0], vh[0], vh[1]);
            mma16816(O[j], ph[0], vl[0], vl[1]);
            mma16816(O[j], ph[1], vh[2], vh[3]);
            mma16816(O[j], pl[1], vh[2], vh[3]);
            mma16816(O[j], ph[1], vl[2], vl[3]);
            mma16816(O[j], ph[2], vh2[0], vh2[1]);
            mma16816(O[j], pl[2], vh2[0], vh2[1]);
            mma16816(O[j], ph[2], vl2[0], vl2[1]);
            mma16816(O[j], ph[3], vh2[2], vh2[3]);
            mma16816(O[j], pl[3], vh2[2], vh2[3]);
            mma16816(O[j], ph[3], vl2[2], vl2[3]);
        }
    }

    const int slot = ((b * QT_N) + qt) * MAXC + chunk;
    float* po = g_po + (size_t)slot * 128 * 64;
#pragma unroll
    for (int j = 0; j < 8; j++) {
        *(float2*)&po[qrow * 64 + j * 8 + 2 * tt]       = make_float2(O[j][0], O[j][1]);
        *(float2*)&po[(qrow + 8) * 64 + j * 8 + 2 * tt] = make_float2(O[j][2], O[j][3]);
    }
    if (tt == 0) {
        g_pm[slot * 128 + qrow]     = m0r * 0.125f;
        g_pm[slot * 128 + qrow + 8] = m1r * 0.125f;
        g_pl[slot * 128 + qrow]     = l0r;
        g_pl[slot * 128 + qrow + 8] = l1r;
    }
}

// ------------------- combine (unchanged) -------------------
__global__ __launch_bounds__(256) void attn_combine_kernel(float* __restrict__ y)
{
    const int qt = blockIdx.x >> 1, half = blockIdx.x & 1, b = blockIdx.y;
    const int nc = min((2 * qt + 2 + CHUNK - 1) / CHUNK, MAXC);
    const int t = threadIdx.x;
    const int r = half * 64 + (t >> 2), c0 = (t & 3) * 16;
    const int base = ((b * QT_N) + qt) * MAXC;

    float M = -1e30f;
#pragma unroll 4
    for (int c = 0; c < nc; c++) M = fmaxf(M, g_pm[(base + c) * 128 + r]);
    float wgt[MAXC];
    float L = 0.0f;
#pragma unroll 4
    for (int c = 0; c < nc; c++) {
        wgt[c] = __expf(g_pm[(base + c) * 128 + r] - M);
        L += g_pl[(base + c) * 128 + r] * wgt[c];
    }
    const float inv = 1.0f / L;

    float acc[16];
#pragma unroll
    for (int k = 0; k < 16; k++) acc[k] = 0.0f;
    for (int c = 0; c < nc; c++) {
        const float* po = g_po + (size_t)(base + c) * 128 * 64 + r * 64 + c0;
        const float wc = wgt[c];
#pragma unroll
        for (int v = 0; v < 4; v++) {
            float4 p4 = *(const float4*)(po + v * 4);
            acc[v*4+0] = fmaf(p4.x, wc, acc[v*4+0]);
            acc[v*4+1] = fmaf(p4.y, wc, acc[v*4+1]);
            acc[v*4+2] = fmaf(p4.z, wc, acc[v*4+2]);
            acc[v*4+3] = fmaf(p4.w, wc, acc[v*4+3]);
        }
    }
    float* Y = y + ((size_t)b * Sn + qt * 128 + r) * Hn + c0;
#pragma unroll
    for (int v = 0; v < 4; v++) {
        *(float4*)(Y + v * 4) = make_float4(acc[v*4+0]*inv, acc[v*4+1]*inv,
                                            acc[v*4+2]*inv, acc[v*4+3]*inv);
    }
}

extern "C" void kernel_launch(void* const* d_in, const int* in_sizes, int n_in,
                              void* d_out, int out_size)
{
    const float* x  = (const float*)d_in[0];
    const float* wq = (const float*)d_in[1];
    const float* bq = (const float*)d_in[2];
    const float* wk = (const float*)d_in[3];
    const float* bk = (const float*)d_in[4];
    const float* wv = (const float*)d_in[5];
    const float* bv = (const float*)d_in[6];
    float* y = (float*)d_out;

    conv_w_kernel<<<(3 * Hn * En + 255) / 256, 256>>>(wq, wk, wv);
    conv_x_kernel<<<(Mn * (En / 8)) / 256, 256>>>(x);
    qkv_mma_kernel<<<dim3(3, Mn / 64), 128>>>(bq, bk, bv);

    cudaFuncSetAttribute(attn_partial_kernel, cudaFuncAttributeMaxDynamicSharedMemorySize, ATT_SMEM);
    attn_partial_kernel<<<dim3(MAXC, QT_N, Bn), 256, ATT_SMEM>>>();

    attn_combine_kernel<<<dim3(2 * QT_N, Bn), 256>>>(y);
}

// round 11
// speedup vs baseline: 1.1423x; 1.1423x over previous
#include <cuda_runtime.h>
#include <cuda_bf16.h>
#include <cstdint>

#define Bn 8
#define Sn 2048
#define En 1024
#define Hn 64
#define Mn (Bn * Sn)
#define QT_N 16
#define CHUNK 4
#define MAXC 8

__device__ uint32_t g_qh[Mn * 32];
__device__ uint32_t g_ql[Mn * 32];
__device__ uint32_t g_kh[Mn * 32];
__device__ uint32_t g_kl[Mn * 32];
__device__ uint32_t g_vth[Bn * Hn * (Sn / 2)];
__device__ uint32_t g_vtl[Bn * Hn * (Sn / 2)];

__device__ float g_po[(size_t)Bn * QT_N * MAXC * 128 * 64];
__device__ float g_pm[Bn * QT_N * MAXC * 128];
__device__ float g_pl[Bn * QT_N * MAXC * 128];
__device__ __nv_bfloat16 g_wt[6 * 64 * En];

__device__ __forceinline__ uint32_t smem_u32(const void* p) {
    uint32_t a;
    asm("{ .reg .u64 t; cvta.to.shared.u64 t, %1; cvt.u32.u64 %0, t; }" : "=r"(a) : "l"(p));
    return a;
}
__device__ __forceinline__ void mma16816(float* c, const uint32_t* a,
                                         uint32_t b0, uint32_t b1) {
    asm volatile(
        "mma.sync.aligned.m16n8k16.row.col.f32.bf16.bf16.f32 "
        "{%0,%1,%2,%3}, {%4,%5,%6,%7}, {%8,%9}, {%0,%1,%2,%3};"
        : "+f"(c[0]), "+f"(c[1]), "+f"(c[2]), "+f"(c[3])
        : "r"(a[0]), "r"(a[1]), "r"(a[2]), "r"(a[3]), "r"(b0), "r"(b1));
}
#define LDMX4(r, ad) \
    asm volatile("ldmatrix.sync.aligned.m8n8.x4.shared.b16 {%0,%1,%2,%3}, [%4];" \
        : "=r"((r)[0]), "=r"((r)[1]), "=r"((r)[2]), "=r"((r)[3]) : "r"(ad))

__device__ __forceinline__ uint32_t pack2bf(float f0, float f1) {
    __nv_bfloat16 b0 = __float2bfloat16(f0);
    __nv_bfloat16 b1 = __float2bfloat16(f1);
    return (uint32_t)__bfloat16_as_ushort(b0) | ((uint32_t)__bfloat16_as_ushort(b1) << 16);
}
__device__ __forceinline__ float lowf(uint32_t u)  { return __int_as_float(u << 16); }
__device__ __forceinline__ float highf(uint32_t u) { return __int_as_float(u & 0xFFFF0000u); }

__device__ __forceinline__ float fexp2(float arg) {
    arg = fmaxf(arg, -120.0f);
    float t = arg + 12582912.0f;
    int iv = __float_as_int(t) - 0x4B400000;
    float f = arg - (t - 12582912.0f);
    float p = 0.00133335581f;
    p = fmaf(p, f, 0.00961804886f);
    p = fmaf(p, f, 0.0555041086f);
    p = fmaf(p, f, 0.240226506f);
    p = fmaf(p, f, 0.693147180f);
    p = fmaf(p, f, 1.0f);
    return __int_as_float(__float_as_int(p) + (iv << 23));
}
#define C2 0.1803368801111204f

// ------------------- conv_w -------------------
__global__ __launch_bounds__(256) void conv_w_kernel(
    const float* __restrict__ wq, const float* __restrict__ wk, const float* __restrict__ wv)
{
    const float* wsrc[3] = {wq, wk, wv};
    int id = blockIdx.x * 256 + threadIdx.x;
    if (id >= 3 * Hn * En) return;
    int mat = id / (Hn * En);
    int rem = id % (Hn * En);
    int n = rem / En, k = rem % En;
    float v = wsrc[mat][(size_t)k * Hn + n];
    __nv_bfloat16 hi = __float2bfloat16(v);
    __nv_bfloat16 lo = __float2bfloat16(v - __bfloat162float(hi));
    g_wt[((size_t)(mat * 2 + 0) * Hn + n) * En + k] = hi;
    g_wt[((size_t)(mat * 2 + 1) * Hn + n) * En + k] = lo;
}

// ------------------- qkv: round-9 version (fused 3 mats, ldmatrix) -------------------
#define KC 32
#define ALD 40
__global__ __launch_bounds__(128) void qkv_mma_kernel(
    const float* __restrict__ x,
    const float* __restrict__ bq, const float* __restrict__ bk, const float* __restrict__ bv)
{
    __shared__ char qsm[40960];
    __nv_bfloat16* sAh = (__nv_bfloat16*)qsm;
    __nv_bfloat16* sAl = (__nv_bfloat16*)(qsm + 5120);
    __nv_bfloat16* sB  = (__nv_bfloat16*)(qsm + 10240);
    const int t = threadIdx.x, w = t >> 5, lane = t & 31;
    const int g = lane >> 2, tt = lane & 3, m0 = blockIdx.x * 64;

    float acc[3][8][4];
#pragma unroll
    for (int m = 0; m < 3; m++)
#pragma unroll
        for (int n = 0; n < 8; n++)
#pragma unroll
            for (int i = 0; i < 4; i++) acc[m][n][i] = 0.0f;

    const int arow = w * 16 + (lane & 15);
    const int acol = (lane >> 4) << 3;
    const int brow = lane & 7;
    const int bcol = ((lane >> 3) & 3) << 3;

    for (int c = 0; c < En / KC; c++) {
        const int k0 = c * KC;
        __syncthreads();
        {
            const int r = t >> 1, ks = (t & 1) * 16;
            const float* xp = x + (size_t)(m0 + r) * En + k0 + ks;
            float f[16];
#pragma unroll
            for (int j = 0; j < 4; j++) {
                float4 v4 = *(const float4*)(xp + j * 4);
                f[j*4+0]=v4.x; f[j*4+1]=v4.y; f[j*4+2]=v4.z; f[j*4+3]=v4.w;
            }
            uint32_t hi[8], lo[8];
#pragma unroll
            for (int j = 0; j < 8; j++) {
                float f0 = f[j*2], f1 = f[j*2+1];
                hi[j] = pack2bf(f0, f1);
                lo[j] = pack2bf(f0 - lowf(hi[j]), f1 - highf(hi[j]));
            }
            uint32_t eo = (uint32_t)(r * ALD + ks);
            *(uint4*)&sAh[eo]     = make_uint4(hi[0], hi[1], hi[2], hi[3]);
            *(uint4*)&sAh[eo + 8] = make_uint4(hi[4], hi[5], hi[6], hi[7]);
            *(uint4*)&sAl[eo]     = make_uint4(lo[0], lo[1], lo[2], lo[3]);
            *(uint4*)&sAl[eo + 8] = make_uint4(lo[4], lo[5], lo[6], lo[7]);
        }
#pragma unroll
        for (int rr = 0; rr < 3; rr++) {
            int r = t + rr * 128;
            const __nv_bfloat16* wp = g_wt + (size_t)r * En + k0;
            uint4 v0 = *(const uint4*)wp;
            uint4 v1 = *(const uint4*)(wp + 8);
            uint4 v2 = *(const uint4*)(wp + 16);
            uint4 v3 = *(const uint4*)(wp + 24);
            uint32_t eo = (uint32_t)(r * ALD);
            *(uint4*)&sB[eo] = v0; *(uint4*)&sB[eo+8] = v1;
            *(uint4*)&sB[eo+16] = v2; *(uint4*)&sB[eo+24] = v3;
        }
        __syncthreads();

        uint32_t aH[2][4], aL[2][4];
#pragma unroll
        for (int ks = 0; ks < 2; ks++) {
            LDMX4(aH[ks], smem_u32(&sAh[arow * ALD + ks * 16 + acol]));
            LDMX4(aL[ks], smem_u32(&sAl[arow * ALD + ks * 16 + acol]));
        }
#pragma unroll
        for (int mat = 0; mat < 3; mat++) {
#pragma unroll
            for (int n8 = 0; n8 < 8; n8++) {
                uint32_t bh[4], bl[4];
                LDMX4(bh, smem_u32(&sB[((mat*2+0)*64 + n8*8 + brow) * ALD + bcol]));
                LDMX4(bl, smem_u32(&sB[((mat*2+1)*64 + n8*8 + brow) * ALD + bcol]));
                mma16816(acc[mat][n8], aH[0], bh[0], bh[1]);
                mma16816(acc[mat][n8], aL[0], bh[0], bh[1]);
                mma16816(acc[mat][n8], aH[0], bl[0], bl[1]);
                mma16816(acc[mat][n8], aH[1], bh[2], bh[3]);
                mma16816(acc[mat][n8], aL[1], bh[2], bh[3]);
                mma16816(acc[mat][n8], aH[1], bl[2], bl[3]);
            }
        }
    }

    const int rl = w * 16 + g;
    {
        uint32_t* gh2[2] = {g_qh, g_kh};
        uint32_t* gl2[2] = {g_ql, g_kl};
        const float* bias2[2] = {bq, bk};
#pragma unroll
        for (int mat = 0; mat < 2; mat++) {
#pragma unroll
            for (int n8 = 0; n8 < 8; n8++) {
                int col = n8 * 8 + 2 * tt;
                float b0 = __ldg(bias2[mat] + col), b1 = __ldg(bias2[mat] + col + 1);
                float v00 = acc[mat][n8][0] + b0, v01 = acc[mat][n8][1] + b1;
                float v10 = acc[mat][n8][2] + b0, v11 = acc[mat][n8][3] + b1;
                uint32_t hA = pack2bf(v00, v01);
                uint32_t lA = pack2bf(v00 - lowf(hA), v01 - highf(hA));
                uint32_t hB = pack2bf(v10, v11);
                uint32_t lB = pack2bf(v10 - lowf(hB), v11 - highf(hB));
                size_t iA = (size_t)(m0 + rl) * 32 + n8 * 4 + tt;
                size_t iB = (size_t)(m0 + rl + 8) * 32 + n8 * 4 + tt;
                gh2[mat][iA] = hA; gl2[mat][iA] = lA;
                gh2[mat][iB] = hB; gl2[mat][iB] = lB;
            }
        }
    }
    float* vsm = (float*)(qsm + 10240);
    __syncthreads();
#pragma unroll
    for (int n8 = 0; n8 < 8; n8++) {
        int col = n8 * 8 + 2 * tt;
        float b0 = __ldg(bv + col), b1 = __ldg(bv + col + 1);
        vsm[rl * 66 + col]           = acc[2][n8][0] + b0;
        vsm[rl * 66 + col + 1]       = acc[2][n8][1] + b1;
        vsm[(rl + 8) * 66 + col]     = acc[2][n8][2] + b0;
        vsm[(rl + 8) * 66 + col + 1] = acc[2][n8][3] + b1;
    }
    __syncthreads();
    {
        int h = t >> 1, half = t & 1;
        int bb = m0 >> 11;
        int sp0 = ((m0 & 2047) + half * 32) >> 1;
        uint32_t oh[16], ol[16];
#pragma unroll
        for (int s = 0; s < 16; s++) {
            float a = vsm[(half * 32 + 2 * s) * 66 + h];
            float cc = vsm[(half * 32 + 2 * s + 1) * 66 + h];
            oh[s] = pack2bf(a, cc);
            ol[s] = pack2bf(a - lowf(oh[s]), cc - highf(oh[s]));
        }
        uint32_t* gvh = g_vth + (size_t)(bb * Hn + h) * (Sn / 2) + sp0;
        uint32_t* gvl = g_vtl + (size_t)(bb * Hn + h) * (Sn / 2) + sp0;
#pragma unroll
        for (int q = 0; q < 4; q++) {
            *(uint4*)(gvh + q * 4) = make_uint4(oh[q*4], oh[q*4+1], oh[q*4+2], oh[q*4+3]);
            *(uint4*)(gvl + q * 4) = make_uint4(ol[q*4], ol[q*4+1], ol[q*4+2], ol[q*4+3]);
        }
    }
}

// ------------------- attention partials: 2 blocks/SM -------------------
#define AR64 2304
#define ARQ  4608
#define OFF_KH (2*ARQ)
#define OFF_KL (2*ARQ + AR64)
#define OFF_VH (2*ARQ + 2*AR64)
#define OFF_VL (2*ARQ + 3*AR64)
#define ATT_SMEM ((2*ARQ + 4*AR64) * 4)

__global__ __launch_bounds__(256, 2) void attn_partial_kernel()
{
    const int chunk = blockIdx.x, qt = blockIdx.y, b = blockIdx.z;
    const int nt = 2 * qt + 2;
    const int jt0 = chunk * CHUNK;
    if (jt0 >= nt) return;
    const int jt1 = min(jt0 + CHUNK, nt);

    extern __shared__ uint32_t su[];
    const uint32_t sbase = smem_u32(su);
    const int t = threadIdx.x, w = t >> 5, lane = t & 31;
    const int g = lane >> 2, tt = lane & 3;
    const int qrow = w * 16 + g;

    const int arow = w * 16 + (lane & 15);
    const int acolB = ((lane >> 4) << 3) * 2;
    const int brow = lane & 7;
    const int bcolB = (((lane >> 3) & 3) << 3) * 2;

    {
        const uint4* qh4 = (const uint4*)g_qh;
        const uint4* ql4 = (const uint4*)g_ql;
        size_t gb = ((size_t)b * Sn + qt * 128) * 8;
#pragma unroll
        for (int i = 0; i < 4; i++) {
            int u = t + i * 256, r = u >> 3, c = u & 7;
            *(uint4*)&su[r * 36 + c * 4]       = qh4[gb + r * 8 + c];
            *(uint4*)&su[ARQ + r * 36 + c * 4] = ql4[gb + r * 8 + c];
        }
    }

    float m0r = -1e30f, m1r = -1e30f, l0r = 0.0f, l1r = 0.0f;
    float O[8][4];
#pragma unroll
    for (int j = 0; j < 8; j++)
#pragma unroll
        for (int i = 0; i < 4; i++) O[j][i] = 0.0f;

    __syncthreads();

    for (int jt = jt0; jt < jt1; jt++) {
        if (jt > jt0) __syncthreads();
        {
            const uint4* kh4 = (const uint4*)g_kh;
            const uint4* kl4 = (const uint4*)g_kl;
            const uint4* vh4 = (const uint4*)g_vth;
            const uint4* vl4 = (const uint4*)g_vtl;
            size_t kb = ((size_t)b * Sn + jt * 64) * 8;
#pragma unroll
            for (int i = 0; i < 2; i++) {
                int u = t + i * 256, r = u >> 3, c = u & 7;
                *(uint4*)&su[OFF_KH + r * 36 + c * 4] = kh4[kb + r * 8 + c];
                *(uint4*)&su[OFF_KL + r * 36 + c * 4] = kl4[kb + r * 8 + c];
                size_t vb = (size_t)(b * Hn + r) * 256 + jt * 8 + c;
                *(uint4*)&su[OFF_VH + r * 36 + c * 4] = vh4[vb];
                *(uint4*)&su[OFF_VL + r * 36 + c * 4] = vl4[vb];
            }
        }
        __syncthreads();

        // Reload Q fragments (persistent smem region; frees registers across PV)
        uint32_t aQh[4][4], aQl[4][4];
#pragma unroll
        for (int ks = 0; ks < 4; ks++) {
            uint32_t ad = sbase + arow * 144 + ks * 32 + acolB;
            LDMX4(aQh[ks], ad);
            LDMX4(aQl[ks], ad + ARQ * 4);
        }

        float S[8][4];
#pragma unroll
        for (int j = 0; j < 8; j++)
#pragma unroll
            for (int i = 0; i < 4; i++) S[j][i] = 0.0f;
#pragma unroll
        for (int j = 0; j < 8; j++) {
            uint32_t adh = sbase + (OFF_KH + (j * 8 + brow) * 36) * 4 + bcolB;
            uint32_t adl = sbase + (OFF_KL + (j * 8 + brow) * 36) * 4 + bcolB;
            uint32_t kh[4], kl[4], kh2[4], kl2[4];
            LDMX4(kh, adh);
            LDMX4(kl, adl);
            LDMX4(kh2, adh + 64);
            LDMX4(kl2, adl + 64);
            mma16816(S[j], aQh[0], kh[0], kh[1]);
            mma16816(S[j], aQl[0], kh[0], kh[1]);
            mma16816(S[j], aQh[0], kl[0], kl[1]);
            mma16816(S[j], aQh[1], kh[2], kh[3]);
            mma16816(S[j], aQl[1], kh[2], kh[3]);
            mma16816(S[j], aQh[1], kl[2], kl[3]);
            mma16816(S[j], aQh[2], kh2[0], kh2[1]);
            mma16816(S[j], aQl[2], kh2[0], kh2[1]);
            mma16816(S[j], aQh[2], kl2[0], kl2[1]);
            mma16816(S[j], aQh[3], kh2[2], kh2[3]);
            mma16816(S[j], aQl[3], kh2[2], kh2[3]);
            mma16816(S[j], aQh[3], kl2[2], kl2[3]);
        }

        if (jt >= 2 * qt) {
            int qg0 = qt * 128 + qrow, qg1 = qg0 + 8;
            int kbse = jt * 64;
#pragma unroll
            for (int j = 0; j < 8; j++) {
                int kc = kbse + j * 8 + 2 * tt;
                if (kc     > qg0) S[j][0] = -1e30f;
                if (kc + 1 > qg0) S[j][1] = -1e30f;
                if (kc     > qg1) S[j][2] = -1e30f;
                if (kc + 1 > qg1) S[j][3] = -1e30f;
            }
        }

        float mx0 = -1e30f, mx1 = -1e30f;
#pragma unroll
        for (int j = 0; j < 8; j++) {
            mx0 = fmaxf(mx0, fmaxf(S[j][0], S[j][1]));
            mx1 = fmaxf(mx1, fmaxf(S[j][2], S[j][3]));
        }
        mx0 = fmaxf(mx0, __shfl_xor_sync(0xffffffff, mx0, 1));
        mx0 = fmaxf(mx0, __shfl_xor_sync(0xffffffff, mx0, 2));
        mx1 = fmaxf(mx1, __shfl_xor_sync(0xffffffff, mx1, 1));
        mx1 = fmaxf(mx1, __shfl_xor_sync(0xffffffff, mx1, 2));
        float mn0 = fmaxf(m0r, mx0), mn1 = fmaxf(m1r, mx1);
        float al0 = fexp2((m0r - mn0) * C2), al1 = fexp2((m1r - mn1) * C2);
        l0r *= al0; l1r *= al1;
#pragma unroll
        for (int j = 0; j < 8; j++) {
            O[j][0] *= al0; O[j][1] *= al0; O[j][2] *= al1; O[j][3] *= al1;
        }

        uint32_t ph[4][4], pl[4][4];
        float s0 = 0.0f, s1 = 0.0f;
#pragma unroll
        for (int j = 0; j < 8; j++) {
            float p0 = fexp2((S[j][0] - mn0) * C2);
            float p1 = fexp2((S[j][1] - mn0) * C2);
            float p2 = fexp2((S[j][2] - mn1) * C2);
            float p3 = fexp2((S[j][3] - mn1) * C2);
            s0 += p0 + p1; s1 += p2 + p3;
            uint32_t h01 = pack2bf(p0, p1);
            uint32_t l01 = pack2bf(p0 - lowf(h01), p1 - highf(h01));
            uint32_t h23 = pack2bf(p2, p3);
            uint32_t l23 = pack2bf(p2 - lowf(h23), p3 - highf(h23));
            int s = j >> 1;
            if (!(j & 1)) { ph[s][0] = h01; ph[s][1] = h23; pl[s][0] = l01; pl[s][1] = l23; }
            else          { ph[s][2] = h01; ph[s][3] = h23; pl[s][2] = l01; pl[s][3] = l23; }
        }
        s0 += __shfl_xor_sync(0xffffffff, s0, 1);
        s0 += __shfl_xor_sync(0xffffffff, s0, 2);
        s1 += __shfl_xor_sync(0xffffffff, s1, 1);
        s1 += __shfl_xor_sync(0xffffffff, s1, 2);
        l0r += s0; l1r += s1;
        m0r = mn0; m1r = mn1;

#pragma unroll
        for (int j = 0; j < 8; j++) {
            uint32_t adh = sbase + (OFF_VH + (j * 8 + brow) * 36) * 4 + bcolB;
            uint32_t adl = sbase + (OFF_VL + (j * 8 + brow) * 36) * 4 + bcolB;
            uint32_t vh[4], vl[4], vh2[4], vl2[4];
            LDMX4(vh, adh);
            LDMX4(vl, adl);
            LDMX4(vh2, adh + 64);
            LDMX4(vl2, adl + 64);
            mma16816(O[j], ph[0], vh[0], vh[1]);
            mma16816(O[j], pl[0], vh[0], vh[1]);
            mma16816(O[j], ph[0], vl[0], vl[1]);
            mma16816(O[j], ph[1], vh[2], vh[3]);
            mma16816(O[j], pl[1], vh[2], vh[3]);
            mma16816(O[j], ph[1], vl[2], vl[3]);
            mma16816(O[j], ph[2], vh2[0], vh2[1]);
            mma16816(O[j], pl[2], vh2[0], vh2[1]);
            mma16816(O[j], ph[2], vl2[0], vl2[1]);
            mma16816(O[j], ph[3], vh2[2], vh2[3]);
            mma16816(O[j], pl[3], vh2[2], vh2[3]);
            mma16816(O[j], ph[3], vl2[2], vl2[3]);
        }
    }

    const int slot = ((b * QT_N) + qt) * MAXC + chunk;
    float* po = g_po + (size_t)slot * 128 * 64;
#pragma unroll
    for (int j = 0; j < 8; j++) {
        *(float2*)&po[qrow * 64 + j * 8 + 2 * tt]       = make_float2(O[j][0], O[j][1]);
        *(float2*)&po[(qrow + 8) * 64 + j * 8 + 2 * tt] = make_float2(O[j][2], O[j][3]);
    }
    if (tt == 0) {
        g_pm[slot * 128 + qrow]     = m0r * 0.125f;
        g_pm[slot * 128 + qrow + 8] = m1r * 0.125f;
        g_pl[slot * 128 + qrow]     = l0r;
        g_pl[slot * 128 + qrow + 8] = l1r;
    }
}

// ------------------- combine (unchanged) -------------------
__global__ __launch_bounds__(256) void attn_combine_kernel(float* __restrict__ y)
{
    const int qt = blockIdx.x >> 1, half = blockIdx.x & 1, b = blockIdx.y;
    const int nc = min((2 * qt + 2 + CHUNK - 1) / CHUNK, MAXC);
    const int t = threadIdx.x;
    const int r = half * 64 + (t >> 2), c0 = (t & 3) * 16;
    const int base = ((b * QT_N) + qt) * MAXC;

    float M = -1e30f;
#pragma unroll 4
    for (int c = 0; c < nc; c++) M = fmaxf(M, g_pm[(base + c) * 128 + r]);
    float wgt[MAXC];
    float L = 0.0f;
#pragma unroll 4
    for (int c = 0; c < nc; c++) {
        wgt[c] = __expf(g_pm[(base + c) * 128 + r] - M);
        L += g_pl[(base + c) * 128 + r] * wgt[c];
    }
    const float inv = 1.0f / L;

    float acc[16];
#pragma unroll
    for (int k = 0; k < 16; k++) acc[k] = 0.0f;
    for (int c = 0; c < nc; c++) {
        const float* po = g_po + (size_t)(base + c) * 128 * 64 + r * 64 + c0;
        const float wc = wgt[c];
#pragma unroll
        for (int v = 0; v < 4; v++) {
            float4 p4 = *(const float4*)(po + v * 4);
            acc[v*4+0] = fmaf(p4.x, wc, acc[v*4+0]);
            acc[v*4+1] = fmaf(p4.y, wc, acc[v*4+1]);
            acc[v*4+2] = fmaf(p4.z, wc, acc[v*4+2]);
            acc[v*4+3] = fmaf(p4.w, wc, acc[v*4+3]);
        }
    }
    float* Y = y + ((size_t)b * Sn + qt * 128 + r) * Hn + c0;
#pragma unroll
    for (int v = 0; v < 4; v++) {
        *(float4*)(Y + v * 4) = make_float4(acc[v*4+0]*inv, acc[v*4+1]*inv,
                                            acc[v*4+2]*inv, acc[v*4+3]*inv);
    }
}

extern "C" void kernel_launch(void* const* d_in, const int* in_sizes, int n_in,
                              void* d_out, int out_size)
{
    const float* x  = (const float*)d_in[0];
    const float* wq = (const float*)d_in[1];
    const float* bq = (const float*)d_in[2];
    const float* wk = (const float*)d_in[3];
    const float* bk = (const float*)d_in[4];
    const float* wv = (const float*)d_in[5];
    const float* bv = (const float*)d_in[6];
    float* y = (float*)d_out;

    conv_w_kernel<<<(3 * Hn * En + 255) / 256, 256>>>(wq, wk, wv);
    qkv_mma_kernel<<<Mn / 64, 128>>>(x, bq, bk, bv);

    cudaFuncSetAttribute(attn_partial_kernel, cudaFuncAttributeMaxDynamicSharedMemorySize, ATT_SMEM);
    attn_partial_kernel<<<dim3(MAXC, QT_N, Bn), 256, ATT_SMEM>>>();

    attn_combine_kernel<<<dim3(2 * QT_N, Bn), 256>>>(y);
}

// round 12
// speedup vs baseline: 1.4562x; 1.2747x over previous
#include <cuda_runtime.h>
#include <cuda_bf16.h>
#include <cstdint>

#define Bn 8
#define Sn 2048
#define En 1024
#define Hn 64
#define Mn (Bn * Sn)
#define QT_N 16
#define CHUNK 4
#define MAXC 8

__device__ uint32_t g_qh[Mn * 32];
__device__ uint32_t g_ql[Mn * 32];
__device__ uint32_t g_kh[Mn * 32];
__device__ uint32_t g_kl[Mn * 32];
__device__ uint32_t g_vth[Bn * Hn * (Sn / 2)];
__device__ uint32_t g_vtl[Bn * Hn * (Sn / 2)];

__device__ float g_po[(size_t)Bn * QT_N * MAXC * 128 * 64];
__device__ float g_pm[Bn * QT_N * MAXC * 128];
__device__ float g_pl[Bn * QT_N * MAXC * 128];
__device__ __nv_bfloat16 g_wt[6 * 64 * En];

__device__ __forceinline__ uint32_t smem_u32(const void* p) {
    uint32_t a;
    asm("{ .reg .u64 t; cvta.to.shared.u64 t, %1; cvt.u32.u64 %0, t; }" : "=r"(a) : "l"(p));
    return a;
}
__device__ __forceinline__ void mma16816(float* c, const uint32_t* a,
                                         uint32_t b0, uint32_t b1) {
    asm volatile(
        "mma.sync.aligned.m16n8k16.row.col.f32.bf16.bf16.f32 "
        "{%0,%1,%2,%3}, {%4,%5,%6,%7}, {%8,%9}, {%0,%1,%2,%3};"
        : "+f"(c[0]), "+f"(c[1]), "+f"(c[2]), "+f"(c[3])
        : "r"(a[0]), "r"(a[1]), "r"(a[2]), "r"(a[3]), "r"(b0), "r"(b1));
}
#define LDMX4(r, ad) \
    asm volatile("ldmatrix.sync.aligned.m8n8.x4.shared.b16 {%0,%1,%2,%3}, [%4];" \
        : "=r"((r)[0]), "=r"((r)[1]), "=r"((r)[2]), "=r"((r)[3]) : "r"(ad))
#define CPA16(dst, src) asm volatile("cp.async.cg.shared.global [%0], [%1], 16;" :: "r"(dst), "l"(src))
#define CPC()  asm volatile("cp.async.commit_group;")
#define CPW1() asm volatile("cp.async.wait_group 1;" ::: "memory")
#define CPW0() asm volatile("cp.async.wait_group 0;" ::: "memory")

__device__ __forceinline__ uint32_t pack2bf(float f0, float f1) {
    __nv_bfloat16 b0 = __float2bfloat16(f0);
    __nv_bfloat16 b1 = __float2bfloat16(f1);
    return (uint32_t)__bfloat16_as_ushort(b0) | ((uint32_t)__bfloat16_as_ushort(b1) << 16);
}
__device__ __forceinline__ float lowf(uint32_t u)  { return __int_as_float(u << 16); }
__device__ __forceinline__ float highf(uint32_t u) { return __int_as_float(u & 0xFFFF0000u); }

__device__ __forceinline__ float fexp2(float arg) {
    arg = fmaxf(arg, -120.0f);
    float t = arg + 12582912.0f;
    int iv = __float_as_int(t) - 0x4B400000;
    float f = arg - (t - 12582912.0f);
    float p = 0.00133335581f;
    p = fmaf(p, f, 0.00961804886f);
    p = fmaf(p, f, 0.0555041086f);
    p = fmaf(p, f, 0.240226506f);
    p = fmaf(p, f, 0.693147180f);
    p = fmaf(p, f, 1.0f);
    return __int_as_float(__float_as_int(p) + (iv << 23));
}
#define C2 0.1803368801111204f

// ------------------- conv_w -------------------
__global__ __launch_bounds__(256) void conv_w_kernel(
    const float* __restrict__ wq, const float* __restrict__ wk, const float* __restrict__ wv)
{
    const float* wsrc[3] = {wq, wk, wv};
    int id = blockIdx.x * 256 + threadIdx.x;
    if (id >= 3 * Hn * En) return;
    int mat = id / (Hn * En);
    int rem = id % (Hn * En);
    int n = rem / En, k = rem % En;
    float v = wsrc[mat][(size_t)k * Hn + n];
    __nv_bfloat16 hi = __float2bfloat16(v);
    __nv_bfloat16 lo = __float2bfloat16(v - __bfloat162float(hi));
    g_wt[((size_t)(mat * 2 + 0) * Hn + n) * En + k] = hi;
    g_wt[((size_t)(mat * 2 + 1) * Hn + n) * En + k] = lo;
}

// ------------------- qkv: cp.async double-buffered mainloop -------------------
#define KC 32
#define ALD 40
#define QS_AH 0
#define QS_AL 5120
#define QS_B  10240
#define QS_BSZ 30720
#define QKV_SMEM (QS_B + 2 * QS_BSZ)   // 71680 B

__global__ __launch_bounds__(128) void qkv_mma_kernel(
    const float* __restrict__ x,
    const float* __restrict__ bq, const float* __restrict__ bk, const float* __restrict__ bv)
{
    extern __shared__ char qsm[];
    __nv_bfloat16* sAh = (__nv_bfloat16*)(qsm + QS_AH);
    __nv_bfloat16* sAl = (__nv_bfloat16*)(qsm + QS_AL);
    const uint32_t sb = smem_u32(qsm);
    const int t = threadIdx.x, w = t >> 5, lane = t & 31;
    const int g = lane >> 2, tt = lane & 3, m0 = blockIdx.x * 64;

    float acc[3][8][4];
#pragma unroll
    for (int m = 0; m < 3; m++)
#pragma unroll
        for (int n = 0; n < 8; n++)
#pragma unroll
            for (int i = 0; i < 4; i++) acc[m][n][i] = 0.0f;

    const int arow = w * 16 + (lane & 15);
    const int acol = (lane >> 4) << 3;
    const int brow = lane & 7;
    const int bcol = ((lane >> 3) & 3) << 3;

    const int xrow = t >> 1, xoff = (t & 1) * 16;
    const float* xbase = x + (size_t)(m0 + xrow) * En + xoff;

    // prologue: x(0) regs + cp.async B(0) -> stage 0
    float4 xr[4];
    xr[0] = *(const float4*)xbase;
    xr[1] = *(const float4*)(xbase + 4);
    xr[2] = *(const float4*)(xbase + 8);
    xr[3] = *(const float4*)(xbase + 12);
#pragma unroll
    for (int i = 0; i < 12; i++) {
        int idx = t + i * 128, row = idx >> 2, q = idx & 3;
        CPA16(sb + QS_B + row * 80 + q * 16,
              (const char*)(g_wt + (size_t)row * En) + q * 16);
    }
    CPC();

    for (int c = 0; c < 32; c++) {
        const int buf = c & 1;
        __syncthreads();                 // compute(c-1) done reading A and B[buf^1... all]

        // convert xr(c) -> A smem
        {
            float f[16];
            f[0]=xr[0].x; f[1]=xr[0].y; f[2]=xr[0].z; f[3]=xr[0].w;
            f[4]=xr[1].x; f[5]=xr[1].y; f[6]=xr[1].z; f[7]=xr[1].w;
            f[8]=xr[2].x; f[9]=xr[2].y; f[10]=xr[2].z; f[11]=xr[2].w;
            f[12]=xr[3].x; f[13]=xr[3].y; f[14]=xr[3].z; f[15]=xr[3].w;
            uint32_t hi[8], lo[8];
#pragma unroll
            for (int j = 0; j < 8; j++) {
                hi[j] = pack2bf(f[2*j], f[2*j+1]);
                lo[j] = pack2bf(f[2*j] - lowf(hi[j]), f[2*j+1] - highf(hi[j]));
            }
            uint32_t eo = (uint32_t)(xrow * ALD + xoff);
            *(uint4*)&sAh[eo]     = make_uint4(hi[0], hi[1], hi[2], hi[3]);
            *(uint4*)&sAh[eo + 8] = make_uint4(hi[4], hi[5], hi[6], hi[7]);
            *(uint4*)&sAl[eo]     = make_uint4(lo[0], lo[1], lo[2], lo[3]);
            *(uint4*)&sAl[eo + 8] = make_uint4(lo[4], lo[5], lo[6], lo[7]);
        }

        // prefetch chunk c+1: B via cp.async into alt stage; x into regs
        if (c < 31) {
            const int k1 = (c + 1) * KC;
#pragma unroll
            for (int i = 0; i < 12; i++) {
                int idx = t + i * 128, row = idx >> 2, q = idx & 3;
                CPA16(sb + QS_B + (buf ^ 1) * QS_BSZ + row * 80 + q * 16,
                      (const char*)(g_wt + (size_t)row * En + k1) + q * 16);
            }
            CPC();
            const float* xp = xbase + k1;
            xr[0] = *(const float4*)xp;
            xr[1] = *(const float4*)(xp + 4);
            xr[2] = *(const float4*)(xp + 8);
            xr[3] = *(const float4*)(xp + 12);
            CPW1();                      // B(c) landed; B(c+1) in flight
        } else {
            CPW0();
        }
        __syncthreads();

        // compute(c)
        const uint32_t bbase = sb + QS_B + buf * QS_BSZ;
        uint32_t aH[2][4], aL[2][4];
#pragma unroll
        for (int ks = 0; ks < 2; ks++) {
            uint32_t ad = sb + QS_AH + (arow * ALD + ks * 16 + acol) * 2;
            LDMX4(aH[ks], ad);
            LDMX4(aL[ks], ad + QS_AL);
        }
#pragma unroll
        for (int mat = 0; mat < 3; mat++) {
#pragma unroll
            for (int n8 = 0; n8 < 8; n8++) {
                uint32_t bh[4], bl[4];
                LDMX4(bh, bbase + (((mat*2+0)*64 + n8*8 + brow) * ALD + bcol) * 2);
                LDMX4(bl, bbase + (((mat*2+1)*64 + n8*8 + brow) * ALD + bcol) * 2);
                mma16816(acc[mat][n8], aH[0], bh[0], bh[1]);
                mma16816(acc[mat][n8], aL[0], bh[0], bh[1]);
                mma16816(acc[mat][n8], aH[0], bl[0], bl[1]);
                mma16816(acc[mat][n8], aH[1], bh[2], bh[3]);
                mma16816(acc[mat][n8], aL[1], bh[2], bh[3]);
                mma16816(acc[mat][n8], aH[1], bl[2], bl[3]);
            }
        }
    }

    // ---- epilogue: Q,K packed hi/lo ----
    const int rl = w * 16 + g;
    {
        uint32_t* gh2[2] = {g_qh, g_kh};
        uint32_t* gl2[2] = {g_ql, g_kl};
        const float* bias2[2] = {bq, bk};
#pragma unroll
        for (int mat = 0; mat < 2; mat++) {
#pragma unroll
            for (int n8 = 0; n8 < 8; n8++) {
                int col = n8 * 8 + 2 * tt;
                float b0 = __ldg(bias2[mat] + col), b1 = __ldg(bias2[mat] + col + 1);
                float v00 = acc[mat][n8][0] + b0, v01 = acc[mat][n8][1] + b1;
                float v10 = acc[mat][n8][2] + b0, v11 = acc[mat][n8][3] + b1;
                uint32_t hA = pack2bf(v00, v01);
                uint32_t lA = pack2bf(v00 - lowf(hA), v01 - highf(hA));
                uint32_t hB = pack2bf(v10, v11);
                uint32_t lB = pack2bf(v10 - lowf(hB), v11 - highf(hB));
                size_t iA = (size_t)(m0 + rl) * 32 + n8 * 4 + tt;
                size_t iB = (size_t)(m0 + rl + 8) * 32 + n8 * 4 + tt;
                gh2[mat][iA] = hA; gl2[mat][iA] = lA;
                gh2[mat][iB] = hB; gl2[mat][iB] = lB;
            }
        }
    }
    // ---- epilogue: V transpose via smem ----
    float* vsm = (float*)(qsm + QS_B);
    __syncthreads();
#pragma unroll
    for (int n8 = 0; n8 < 8; n8++) {
        int col = n8 * 8 + 2 * tt;
        float b0 = __ldg(bv + col), b1 = __ldg(bv + col + 1);
        vsm[rl * 66 + col]           = acc[2][n8][0] + b0;
        vsm[rl * 66 + col + 1]       = acc[2][n8][1] + b1;
        vsm[(rl + 8) * 66 + col]     = acc[2][n8][2] + b0;
        vsm[(rl + 8) * 66 + col + 1] = acc[2][n8][3] + b1;
    }
    __syncthreads();
    {
        int h = t >> 1, half = t & 1;
        int bb = m0 >> 11;
        int sp0 = ((m0 & 2047) + half * 32) >> 1;
        uint32_t oh[16], ol[16];
#pragma unroll
        for (int s = 0; s < 16; s++) {
            float a = vsm[(half * 32 + 2 * s) * 66 + h];
            float cc = vsm[(half * 32 + 2 * s + 1) * 66 + h];
            oh[s] = pack2bf(a, cc);
            ol[s] = pack2bf(a - lowf(oh[s]), cc - highf(oh[s]));
        }
        uint32_t* gvh = g_vth + (size_t)(bb * Hn + h) * (Sn / 2) + sp0;
        uint32_t* gvl = g_vtl + (size_t)(bb * Hn + h) * (Sn / 2) + sp0;
#pragma unroll
        for (int q = 0; q < 4; q++) {
            *(uint4*)(gvh + q * 4) = make_uint4(oh[q*4], oh[q*4+1], oh[q*4+2], oh[q*4+3]);
            *(uint4*)(gvl + q * 4) = make_uint4(ol[q*4], ol[q*4+1], ol[q*4+2], ol[q*4+3]);
        }
    }
}

// ------------------- attention partials (round-11, passing) -------------------
#define AR64 2304
#define ARQ  4608
#define OFF_KH (2*ARQ)
#define OFF_KL (2*ARQ + AR64)
#define OFF_VH (2*ARQ + 2*AR64)
#define OFF_VL (2*ARQ + 3*AR64)
#define ATT_SMEM ((2*ARQ + 4*AR64) * 4)

__global__ __launch_bounds__(256, 2) void attn_partial_kernel()
{
    const int chunk = blockIdx.x, qt = blockIdx.y, b = blockIdx.z;
    const int nt = 2 * qt + 2;
    const int jt0 = chunk * CHUNK;
    if (jt0 >= nt) return;
    const int jt1 = min(jt0 + CHUNK, nt);

    extern __shared__ uint32_t su[];
    const uint32_t sbase = smem_u32(su);
    const int t = threadIdx.x, w = t >> 5, lane = t & 31;
    const int g = lane >> 2, tt = lane & 3;
    const int qrow = w * 16 + g;

    const int arow = w * 16 + (lane & 15);
    const int acolB = ((lane >> 4) << 3) * 2;
    const int brow = lane & 7;
    const int bcolB = (((lane >> 3) & 3) << 3) * 2;

    {
        const uint4* qh4 = (const uint4*)g_qh;
        const uint4* ql4 = (const uint4*)g_ql;
        size_t gb = ((size_t)b * Sn + qt * 128) * 8;
#pragma unroll
        for (int i = 0; i < 4; i++) {
            int u = t + i * 256, r = u >> 3, c = u & 7;
            *(uint4*)&su[r * 36 + c * 4]       = qh4[gb + r * 8 + c];
            *(uint4*)&su[ARQ + r * 36 + c * 4] = ql4[gb + r * 8 + c];
        }
    }

    float m0r = -1e30f, m1r = -1e30f, l0r = 0.0f, l1r = 0.0f;
    float O[8][4];
#pragma unroll
    for (int j = 0; j < 8; j++)
#pragma unroll
        for (int i = 0; i < 4; i++) O[j][i] = 0.0f;

    __syncthreads();

    for (int jt = jt0; jt < jt1; jt++) {
        if (jt > jt0) __syncthreads();
        {
            const uint4* kh4 = (const uint4*)g_kh;
            const uint4* kl4 = (const uint4*)g_kl;
            const uint4* vh4 = (const uint4*)g_vth;
            const uint4* vl4 = (const uint4*)g_vtl;
            size_t kb = ((size_t)b * Sn + jt * 64) * 8;
#pragma unroll
            for (int i = 0; i < 2; i++) {
                int u = t + i * 256, r = u >> 3, c = u & 7;
                *(uint4*)&su[OFF_KH + r * 36 + c * 4] = kh4[kb + r * 8 + c];
                *(uint4*)&su[OFF_KL + r * 36 + c * 4] = kl4[kb + r * 8 + c];
                size_t vb = (size_t)(b * Hn + r) * 256 + jt * 8 + c;
                *(uint4*)&su[OFF_VH + r * 36 + c * 4] = vh4[vb];
                *(uint4*)&su[OFF_VL + r * 36 + c * 4] = vl4[vb];
            }
        }
        __syncthreads();

        uint32_t aQh[4][4], aQl[4][4];
#pragma unroll
        for (int ks = 0; ks < 4; ks++) {
            uint32_t ad = sbase + arow * 144 + ks * 32 + acolB;
            LDMX4(aQh[ks], ad);
            LDMX4(aQl[ks], ad + ARQ * 4);
        }

        float S[8][4];
#pragma unroll
        for (int j = 0; j < 8; j++)
#pragma unroll
            for (int i = 0; i < 4; i++) S[j][i] = 0.0f;
#pragma unroll
        for (int j = 0; j < 8; j++) {
            uint32_t adh = sbase + (OFF_KH + (j * 8 + brow) * 36) * 4 + bcolB;
            uint32_t adl = sbase + (OFF_KL + (j * 8 + brow) * 36) * 4 + bcolB;
            uint32_t kh[4], kl[4], kh2[4], kl2[4];
            LDMX4(kh, adh);
            LDMX4(kl, adl);
            LDMX4(kh2, adh + 64);
            LDMX4(kl2, adl + 64);
            mma16816(S[j], aQh[0], kh[0], kh[1]);
            mma16816(S[j], aQl[0], kh[0], kh[1]);
            mma16816(S[j], aQh[0], kl[0], kl[1]);
            mma16816(S[j], aQh[1], kh[2], kh[3]);
            mma16816(S[j], aQl[1], kh[2], kh[3]);
            mma16816(S[j], aQh[1], kl[2], kl[3]);
            mma16816(S[j], aQh[2], kh2[0], kh2[1]);
            mma16816(S[j], aQl[2], kh2[0], kh2[1]);
            mma16816(S[j], aQh[2], kl2[0], kl2[1]);
            mma16816(S[j], aQh[3], kh2[2], kh2[3]);
            mma16816(S[j], aQl[3], kh2[2], kh2[3]);
            mma16816(S[j], aQh[3], kl2[2], kl2[3]);
        }

        if (jt >= 2 * qt) {
            int qg0 = qt * 128 + qrow, qg1 = qg0 + 8;
            int kbse = jt * 64;
#pragma unroll
            for (int j = 0; j < 8; j++) {
                int kc = kbse + j * 8 + 2 * tt;
                if (kc     > qg0) S[j][0] = -1e30f;
                if (kc + 1 > qg0) S[j][1] = -1e30f;
                if (kc     > qg1) S[j][2] = -1e30f;
                if (kc + 1 > qg1) S[j][3] = -1e30f;
            }
        }

        float mx0 = -1e30f, mx1 = -1e30f;
#pragma unroll
        for (int j = 0; j < 8; j++) {
            mx0 = fmaxf(mx0, fmaxf(S[j][0], S[j][1]));
            mx1 = fmaxf(mx1, fmaxf(S[j][2], S[j][3]));
        }
        mx0 = fmaxf(mx0, __shfl_xor_sync(0xffffffff, mx0, 1));
        mx0 = fmaxf(mx0, __shfl_xor_sync(0xffffffff, mx0, 2));
        mx1 = fmaxf(mx1, __shfl_xor_sync(0xffffffff, mx1, 1));
        mx1 = fmaxf(mx1, __shfl_xor_sync(0xffffffff, mx1, 2));
        float mn0 = fmaxf(m0r, mx0), mn1 = fmaxf(m1r, mx1);
        float al0 = fexp2((m0r - mn0) * C2), al1 = fexp2((m1r - mn1) * C2);
        l0r *= al0; l1r *= al1;
#pragma unroll
        for (int j = 0; j < 8; j++) {
            O[j][0] *= al0; O[j][1] *= al0; O[j][2] *= al1; O[j][3] *= al1;
        }

        uint32_t ph[4][4], pl[4][4];
        float s0 = 0.0f, s1 = 0.0f;
#pragma unroll
        for (int j = 0; j < 8; j++) {
            float p0 = fexp2((S[j][0] - mn0) * C2);
            float p1 = fexp2((S[j][1] - mn0) * C2);
            float p2 = fexp2((S[j][2] - mn1) * C2);
            float p3 = fexp2((S[j][3] - mn1) * C2);
            s0 += p0 + p1; s1 += p2 + p3;
            uint32_t h01 = pack2bf(p0, p1);
            uint32_t l01 = pack2bf(p0 - lowf(h01), p1 - highf(h01));
            uint32_t h23 = pack2bf(p2, p3);
            uint32_t l23 = pack2bf(p2 - lowf(h23), p3 - highf(h23));
            int s = j >> 1;
            if (!(j & 1)) { ph[s][0] = h01; ph[s][1] = h23; pl[s][0] = l01; pl[s][1] = l23; }
            else          { ph[s][2] = h01; ph[s][3] = h23; pl[s][2] = l01; pl[s][3] = l23; }
        }
        s0 += __shfl_xor_sync(0xffffffff, s0, 1);
        s0 += __shfl_xor_sync(0xffffffff, s0, 2);
        s1 += __shfl_xor_sync(0xffffffff, s1, 1);
        s1 += __shfl_xor_sync(0xffffffff, s1, 2);
        l0r += s0; l1r += s1;
        m0r = mn0; m1r = mn1;

#pragma unroll
        for (int j = 0; j < 8; j++) {
            uint32_t adh = sbase + (OFF_VH + (j * 8 + brow) * 36) * 4 + bcolB;
            uint32_t adl = sbase + (OFF_VL + (j * 8 + brow) * 36) * 4 + bcolB;
            uint32_t vh[4], vl[4], vh2[4], vl2[4];
            LDMX4(vh, adh);
            LDMX4(vl, adl);
            LDMX4(vh2, adh + 64);
            LDMX4(vl2, adl + 64);
            mma16816(O[j], ph[0], vh[0], vh[1]);
            mma16816(O[j], pl[0], vh[0], vh[1]);
            mma16816(O[j], ph[0], vl[0], vl[1]);
            mma16816(O[j], ph[1], vh[2], vh[3]);
            mma16816(O[j], pl[1], vh[2], vh[3]);
            mma16816(O[j], ph[1], vl[2], vl[3]);
            mma16816(O[j], ph[2], vh2[0], vh2[1]);
            mma16816(O[j], pl[2], vh2[0], vh2[1]);
            mma16816(O[j], ph[2], vl2[0], vl2[1]);
            mma16816(O[j], ph[3], vh2[2], vh2[3]);
            mma16816(O[j], pl[3], vh2[2], vh2[3]);
            mma16816(O[j], ph[3], vl2[2], vl2[3]);
        }
    }

    const int slot = ((b * QT_N) + qt) * MAXC + chunk;
    float* po = g_po + (size_t)slot * 128 * 64;
#pragma unroll
    for (int j = 0; j < 8; j++) {
        *(float2*)&po[qrow * 64 + j * 8 + 2 * tt]       = make_float2(O[j][0], O[j][1]);
        *(float2*)&po[(qrow + 8) * 64 + j * 8 + 2 * tt] = make_float2(O[j][2], O[j][3]);
    }
    if (tt == 0) {
        g_pm[slot * 128 + qrow]     = m0r * 0.125f;
        g_pm[slot * 128 + qrow + 8] = m1r * 0.125f;
        g_pl[slot * 128 + qrow]     = l0r;
        g_pl[slot * 128 + qrow + 8] = l1r;
    }
}

// ------------------- combine (unchanged) -------------------
__global__ __launch_bounds__(256) void attn_combine_kernel(float* __restrict__ y)
{
    const int qt = blockIdx.x >> 1, half = blockIdx.x & 1, b = blockIdx.y;
    const int nc = min((2 * qt + 2 + CHUNK - 1) / CHUNK, MAXC);
    const int t = threadIdx.x;
    const int r = half * 64 + (t >> 2), c0 = (t & 3) * 16;
    const int base = ((b * QT_N) + qt) * MAXC;

    float M = -1e30f;
#pragma unroll 4
    for (int c = 0; c < nc; c++) M = fmaxf(M, g_pm[(base + c) * 128 + r]);
    float wgt[MAXC];
    float L = 0.0f;
#pragma unroll 4
    for (int c = 0; c < nc; c++) {
        wgt[c] = __expf(g_pm[(base + c) * 128 + r] - M);
        L += g_pl[(base + c) * 128 + r] * wgt[c];
    }
    const float inv = 1.0f / L;

    float acc[16];
#pragma unroll
    for (int k = 0; k < 16; k++) acc[k] = 0.0f;
    for (int c = 0; c < nc; c++) {
        const float* po = g_po + (size_t)(base + c) * 128 * 64 + r * 64 + c0;
        const float wc = wgt[c];
#pragma unroll
        for (int v = 0; v < 4; v++) {
            float4 p4 = *(const float4*)(po + v * 4);
            acc[v*4+0] = fmaf(p4.x, wc, acc[v*4+0]);
            acc[v*4+1] = fmaf(p4.y, wc, acc[v*4+1]);
            acc[v*4+2] = fmaf(p4.z, wc, acc[v*4+2]);
            acc[v*4+3] = fmaf(p4.w, wc, acc[v*4+3]);
        }
    }
    float* Y = y + ((size_t)b * Sn + qt * 128 + r) * Hn + c0;
#pragma unroll
    for (int v = 0; v < 4; v++) {
        *(float4*)(Y + v * 4) = make_float4(acc[v*4+0]*inv, acc[v*4+1]*inv,
                                            acc[v*4+2]*inv, acc[v*4+3]*inv);
    }
}

extern "C" void kernel_launch(void* const* d_in, const int* in_sizes, int n_in,
                              void* d_out, int out_size)
{
    const float* x  = (const float*)d_in[0];
    const float* wq = (const float*)d_in[1];
    const float* bq = (const float*)d_in[2];
    const float* wk = (const float*)d_in[3];
    const float* bk = (const float*)d_in[4];
    const float* wv = (const float*)d_in[5];
    const float* bv = (const float*)d_in[6];
    float* y = (float*)d_out;

    conv_w_kernel<<<(3 * Hn * En + 255) / 256, 256>>>(wq, wk, wv);

    cudaFuncSetAttribute(qkv_mma_kernel, cudaFuncAttributeMaxDynamicSharedMemorySize, QKV_SMEM);
    qkv_mma_kernel<<<Mn / 64, 128, QKV_SMEM>>>(x, bq, bk, bv);

    cudaFuncSetAttribute(attn_partial_kernel, cudaFuncAttributeMaxDynamicSharedMemorySize, ATT_SMEM);
    attn_partial_kernel<<<dim3(MAXC, QT_N, Bn), 256, ATT_SMEM>>>();

    attn_combine_kernel<<<dim3(2 * QT_N, Bn), 256>>>(y);
}

// round 13
// speedup vs baseline: 1.4812x; 1.0172x over previous
#include <cuda_runtime.h>
#include <cuda_bf16.h>
#include <cstdint>

#define Bn 8
#define Sn 2048
#define En 1024
#define Hn 64
#define Mn (Bn * Sn)
#define QT_N 16
#define CHUNK 4
#define MAXC 8

__device__ uint32_t g_qh[Mn * 32];
__device__ uint32_t g_ql[Mn * 32];
__device__ uint32_t g_kh[Mn * 32];
__device__ uint32_t g_kl[Mn * 32];
__device__ uint32_t g_vth[Bn * Hn * (Sn / 2)];
__device__ uint32_t g_vtl[Bn * Hn * (Sn / 2)];

__device__ float g_po[(size_t)Bn * QT_N * MAXC * 128 * 64];
__device__ float g_pm[Bn * QT_N * MAXC * 128];
__device__ float g_pl[Bn * QT_N * MAXC * 128];
__device__ __nv_bfloat16 g_wt[6 * 64 * En];

__device__ __forceinline__ uint32_t smem_u32(const void* p) {
    uint32_t a;
    asm("{ .reg .u64 t; cvta.to.shared.u64 t, %1; cvt.u32.u64 %0, t; }" : "=r"(a) : "l"(p));
    return a;
}
__device__ __forceinline__ void mma16816(float* c, const uint32_t* a,
                                         uint32_t b0, uint32_t b1) {
    asm volatile(
        "mma.sync.aligned.m16n8k16.row.col.f32.bf16.bf16.f32 "
        "{%0,%1,%2,%3}, {%4,%5,%6,%7}, {%8,%9}, {%0,%1,%2,%3};"
        : "+f"(c[0]), "+f"(c[1]), "+f"(c[2]), "+f"(c[3])
        : "r"(a[0]), "r"(a[1]), "r"(a[2]), "r"(a[3]), "r"(b0), "r"(b1));
}
#define LDMX4(r, ad) \
    asm volatile("ldmatrix.sync.aligned.m8n8.x4.shared.b16 {%0,%1,%2,%3}, [%4];" \
        : "=r"((r)[0]), "=r"((r)[1]), "=r"((r)[2]), "=r"((r)[3]) : "r"(ad))
#define CPA16(dst, src) asm volatile("cp.async.cg.shared.global [%0], [%1], 16;" :: "r"(dst), "l"(src))
#define CPC()  asm volatile("cp.async.commit_group;")
#define CPW1() asm volatile("cp.async.wait_group 1;" ::: "memory")
#define CPW0() asm volatile("cp.async.wait_group 0;" ::: "memory")

__device__ __forceinline__ uint32_t pack2bf(float f0, float f1) {
    __nv_bfloat16 b0 = __float2bfloat16(f0);
    __nv_bfloat16 b1 = __float2bfloat16(f1);
    return (uint32_t)__bfloat16_as_ushort(b0) | ((uint32_t)__bfloat16_as_ushort(b1) << 16);
}
__device__ __forceinline__ float lowf(uint32_t u)  { return __int_as_float(u << 16); }
__device__ __forceinline__ float highf(uint32_t u) { return __int_as_float(u & 0xFFFF0000u); }

__device__ __forceinline__ float fexp2(float arg) {
    arg = fmaxf(arg, -120.0f);
    float t = arg + 12582912.0f;
    int iv = __float_as_int(t) - 0x4B400000;
    float f = arg - (t - 12582912.0f);
    float p = 0.00133335581f;
    p = fmaf(p, f, 0.00961804886f);
    p = fmaf(p, f, 0.0555041086f);
    p = fmaf(p, f, 0.240226506f);
    p = fmaf(p, f, 0.693147180f);
    p = fmaf(p, f, 1.0f);
    return __int_as_float(__float_as_int(p) + (iv << 23));
}
#define C2 0.1803368801111204f

// ------------------- conv_w -------------------
__global__ __launch_bounds__(256) void conv_w_kernel(
    const float* __restrict__ wq, const float* __restrict__ wk, const float* __restrict__ wv)
{
    const float* wsrc[3] = {wq, wk, wv};
    int id = blockIdx.x * 256 + threadIdx.x;
    if (id >= 3 * Hn * En) return;
    int mat = id / (Hn * En);
    int rem = id % (Hn * En);
    int n = rem / En, k = rem % En;
    float v = wsrc[mat][(size_t)k * Hn + n];
    __nv_bfloat16 hi = __float2bfloat16(v);
    __nv_bfloat16 lo = __float2bfloat16(v - __bfloat162float(hi));
    g_wt[((size_t)(mat * 2 + 0) * Hn + n) * En + k] = hi;
    g_wt[((size_t)(mat * 2 + 1) * Hn + n) * En + k] = lo;
}

// ------------------- qkv: cp.async double-buffered (round-12, passing) -------------------
#define KC 32
#define ALD 40
#define QS_AH 0
#define QS_AL 5120
#define QS_B  10240
#define QS_BSZ 30720
#define QKV_SMEM (QS_B + 2 * QS_BSZ)

__global__ __launch_bounds__(128) void qkv_mma_kernel(
    const float* __restrict__ x,
    const float* __restrict__ bq, const float* __restrict__ bk, const float* __restrict__ bv)
{
    extern __shared__ char qsm[];
    __nv_bfloat16* sAh = (__nv_bfloat16*)(qsm + QS_AH);
    __nv_bfloat16* sAl = (__nv_bfloat16*)(qsm + QS_AL);
    const uint32_t sb = smem_u32(qsm);
    const int t = threadIdx.x, w = t >> 5, lane = t & 31;
    const int g = lane >> 2, tt = lane & 3, m0 = blockIdx.x * 64;

    float acc[3][8][4];
#pragma unroll
    for (int m = 0; m < 3; m++)
#pragma unroll
        for (int n = 0; n < 8; n++)
#pragma unroll
            for (int i = 0; i < 4; i++) acc[m][n][i] = 0.0f;

    const int arow = w * 16 + (lane & 15);
    const int acol = (lane >> 4) << 3;
    const int brow = lane & 7;
    const int bcol = ((lane >> 3) & 3) << 3;

    const int xrow = t >> 1, xoff = (t & 1) * 16;
    const float* xbase = x + (size_t)(m0 + xrow) * En + xoff;

    float4 xr[4];
    xr[0] = *(const float4*)xbase;
    xr[1] = *(const float4*)(xbase + 4);
    xr[2] = *(const float4*)(xbase + 8);
    xr[3] = *(const float4*)(xbase + 12);
#pragma unroll
    for (int i = 0; i < 12; i++) {
        int idx = t + i * 128, row = idx >> 2, q = idx & 3;
        CPA16(sb + QS_B + row * 80 + q * 16,
              (const char*)(g_wt + (size_t)row * En) + q * 16);
    }
    CPC();

    for (int c = 0; c < 32; c++) {
        const int buf = c & 1;
        __syncthreads();

        {
            float f[16];
            f[0]=xr[0].x; f[1]=xr[0].y; f[2]=xr[0].z; f[3]=xr[0].w;
            f[4]=xr[1].x; f[5]=xr[1].y; f[6]=xr[1].z; f[7]=xr[1].w;
            f[8]=xr[2].x; f[9]=xr[2].y; f[10]=xr[2].z; f[11]=xr[2].w;
            f[12]=xr[3].x; f[13]=xr[3].y; f[14]=xr[3].z; f[15]=xr[3].w;
            uint32_t hi[8], lo[8];
#pragma unroll
            for (int j = 0; j < 8; j++) {
                hi[j] = pack2bf(f[2*j], f[2*j+1]);
                lo[j] = pack2bf(f[2*j] - lowf(hi[j]), f[2*j+1] - highf(hi[j]));
            }
            uint32_t eo = (uint32_t)(xrow * ALD + xoff);
            *(uint4*)&sAh[eo]     = make_uint4(hi[0], hi[1], hi[2], hi[3]);
            *(uint4*)&sAh[eo + 8] = make_uint4(hi[4], hi[5], hi[6], hi[7]);
            *(uint4*)&sAl[eo]     = make_uint4(lo[0], lo[1], lo[2], lo[3]);
            *(uint4*)&sAl[eo + 8] = make_uint4(lo[4], lo[5], lo[6], lo[7]);
        }

        if (c < 31) {
            const int k1 = (c + 1) * KC;
#pragma unroll
            for (int i = 0; i < 12; i++) {
                int idx = t + i * 128, row = idx >> 2, q = idx & 3;
                CPA16(sb + QS_B + (buf ^ 1) * QS_BSZ + row * 80 + q * 16,
                      (const char*)(g_wt + (size_t)row * En + k1) + q * 16);
            }
            CPC();
            const float* xp = xbase + k1;
            xr[0] = *(const float4*)xp;
            xr[1] = *(const float4*)(xp + 4);
            xr[2] = *(const float4*)(xp + 8);
            xr[3] = *(const float4*)(xp + 12);
            CPW1();
        } else {
            CPW0();
        }
        __syncthreads();

        const uint32_t bbase = sb + QS_B + buf * QS_BSZ;
        uint32_t aH[2][4], aL[2][4];
#pragma unroll
        for (int ks = 0; ks < 2; ks++) {
            uint32_t ad = sb + QS_AH + (arow * ALD + ks * 16 + acol) * 2;
            LDMX4(aH[ks], ad);
            LDMX4(aL[ks], ad + QS_AL);
        }
#pragma unroll
        for (int mat = 0; mat < 3; mat++) {
#pragma unroll
            for (int n8 = 0; n8 < 8; n8++) {
                uint32_t bh[4], bl[4];
                LDMX4(bh, bbase + (((mat*2+0)*64 + n8*8 + brow) * ALD + bcol) * 2);
                LDMX4(bl, bbase + (((mat*2+1)*64 + n8*8 + brow) * ALD + bcol) * 2);
                mma16816(acc[mat][n8], aH[0], bh[0], bh[1]);
                mma16816(acc[mat][n8], aL[0], bh[0], bh[1]);
                mma16816(acc[mat][n8], aH[0], bl[0], bl[1]);
                mma16816(acc[mat][n8], aH[1], bh[2], bh[3]);
                mma16816(acc[mat][n8], aL[1], bh[2], bh[3]);
                mma16816(acc[mat][n8], aH[1], bl[2], bl[3]);
            }
        }
    }

    const int rl = w * 16 + g;
    {
        uint32_t* gh2[2] = {g_qh, g_kh};
        uint32_t* gl2[2] = {g_ql, g_kl};
        const float* bias2[2] = {bq, bk};
#pragma unroll
        for (int mat = 0; mat < 2; mat++) {
#pragma unroll
            for (int n8 = 0; n8 < 8; n8++) {
                int col = n8 * 8 + 2 * tt;
                float b0 = __ldg(bias2[mat] + col), b1 = __ldg(bias2[mat] + col + 1);
                float v00 = acc[mat][n8][0] + b0, v01 = acc[mat][n8][1] + b1;
                float v10 = acc[mat][n8][2] + b0, v11 = acc[mat][n8][3] + b1;
                uint32_t hA = pack2bf(v00, v01);
                uint32_t lA = pack2bf(v00 - lowf(hA), v01 - highf(hA));
                uint32_t hB = pack2bf(v10, v11);
                uint32_t lB = pack2bf(v10 - lowf(hB), v11 - highf(hB));
                size_t iA = (size_t)(m0 + rl) * 32 + n8 * 4 + tt;
                size_t iB = (size_t)(m0 + rl + 8) * 32 + n8 * 4 + tt;
                gh2[mat][iA] = hA; gl2[mat][iA] = lA;
                gh2[mat][iB] = hB; gl2[mat][iB] = lB;
            }
        }
    }
    float* vsm = (float*)(qsm + QS_B);
    __syncthreads();
#pragma unroll
    for (int n8 = 0; n8 < 8; n8++) {
        int col = n8 * 8 + 2 * tt;
        float b0 = __ldg(bv + col), b1 = __ldg(bv + col + 1);
        vsm[rl * 66 + col]           = acc[2][n8][0] + b0;
        vsm[rl * 66 + col + 1]       = acc[2][n8][1] + b1;
        vsm[(rl + 8) * 66 + col]     = acc[2][n8][2] + b0;
        vsm[(rl + 8) * 66 + col + 1] = acc[2][n8][3] + b1;
    }
    __syncthreads();
    {
        int h = t >> 1, half = t & 1;
        int bb = m0 >> 11;
        int sp0 = ((m0 & 2047) + half * 32) >> 1;
        uint32_t oh[16], ol[16];
#pragma unroll
        for (int s = 0; s < 16; s++) {
            float a = vsm[(half * 32 + 2 * s) * 66 + h];
            float cc = vsm[(half * 32 + 2 * s + 1) * 66 + h];
            oh[s] = pack2bf(a, cc);
            ol[s] = pack2bf(a - lowf(oh[s]), cc - highf(oh[s]));
        }
        uint32_t* gvh = g_vth + (size_t)(bb * Hn + h) * (Sn / 2) + sp0;
        uint32_t* gvl = g_vtl + (size_t)(bb * Hn + h) * (Sn / 2) + sp0;
#pragma unroll
        for (int q = 0; q < 4; q++) {
            *(uint4*)(gvh + q * 4) = make_uint4(oh[q*4], oh[q*4+1], oh[q*4+2], oh[q*4+3]);
            *(uint4*)(gvl + q * 4) = make_uint4(ol[q*4], ol[q*4+1], ol[q*4+2], ol[q*4+3]);
        }
    }
}

// ------------------- attention partials: double-buffered KV via cp.async -------------------
#define AR64 2304
#define ARQ  4608
#define OFF_ST0 (2*ARQ)
#define STG_SZ  (4*AR64)
#define ATT_SMEM ((2*ARQ + 2*STG_SZ) * 4)   // 110592 B

__global__ __launch_bounds__(256, 2) void attn_partial_kernel()
{
    const int chunk = blockIdx.x, qt = blockIdx.y, b = blockIdx.z;
    const int nt = 2 * qt + 2;
    const int jt0 = chunk * CHUNK;
    if (jt0 >= nt) return;
    const int jt1 = min(jt0 + CHUNK, nt);

    extern __shared__ uint32_t su[];
    const uint32_t sbase = smem_u32(su);
    const int t = threadIdx.x, w = t >> 5, lane = t & 31;
    const int g = lane >> 2, tt = lane & 3;
    const int qrow = w * 16 + g;

    const int arow = w * 16 + (lane & 15);
    const int acolB = ((lane >> 4) << 3) * 2;
    const int brow = lane & 7;
    const int bcolB = (((lane >> 3) & 3) << 3) * 2;

    // stage Q (regular stores; persistent)
    {
        const uint4* qh4 = (const uint4*)g_qh;
        const uint4* ql4 = (const uint4*)g_ql;
        size_t gb = ((size_t)b * Sn + qt * 128) * 8;
#pragma unroll
        for (int i = 0; i < 4; i++) {
            int u = t + i * 256, r = u >> 3, c = u & 7;
            *(uint4*)&su[r * 36 + c * 4]       = qh4[gb + r * 8 + c];
            *(uint4*)&su[ARQ + r * 36 + c * 4] = ql4[gb + r * 8 + c];
        }
    }

    // prologue: cp.async KV(jt0) -> stage 0
    const int sr = t >> 3, scc = t & 7;     // row 0..31(+32), uint4-col 0..7
    {
        size_t kb = ((size_t)b * Sn + jt0 * 64) * 8;
#pragma unroll
        for (int i = 0; i < 2; i++) {
            int r = sr + i * 32;
            uint32_t dst = sbase + (OFF_ST0 + r * 36 + scc * 4) * 4;
            CPA16(dst,               (const char*)((const uint4*)g_kh + kb + r * 8 + scc));
            CPA16(dst + AR64 * 4,    (const char*)((const uint4*)g_kl + kb + r * 8 + scc));
            size_t vb = (size_t)(b * Hn + r) * 256 + jt0 * 8 + scc;
            CPA16(dst + 2*AR64 * 4,  (const char*)((const uint4*)g_vth + vb));
            CPA16(dst + 3*AR64 * 4,  (const char*)((const uint4*)g_vtl + vb));
        }
        CPC();
    }

    float m0r = -1e30f, m1r = -1e30f, l0r = 0.0f, l1r = 0.0f;
    float O[8][4];
#pragma unroll
    for (int j = 0; j < 8; j++)
#pragma unroll
        for (int i = 0; i < 4; i++) O[j][i] = 0.0f;

    for (int jt = jt0; jt < jt1; jt++) {
        const int buf = (jt - jt0) & 1;
        // prefetch next tile into other stage
        if (jt + 1 < jt1) {
            size_t kb = ((size_t)b * Sn + (jt + 1) * 64) * 8;
            uint32_t stb = OFF_ST0 + (buf ^ 1) * STG_SZ;
#pragma unroll
            for (int i = 0; i < 2; i++) {
                int r = sr + i * 32;
                uint32_t dst = sbase + (stb + r * 36 + scc * 4) * 4;
                CPA16(dst,              (const char*)((const uint4*)g_kh + kb + r * 8 + scc));
                CPA16(dst + AR64 * 4,   (const char*)((const uint4*)g_kl + kb + r * 8 + scc));
                size_t vb = (size_t)(b * Hn + r) * 256 + (jt + 1) * 8 + scc;
                CPA16(dst + 2*AR64 * 4, (const char*)((const uint4*)g_vth + vb));
                CPA16(dst + 3*AR64 * 4, (const char*)((const uint4*)g_vtl + vb));
            }
            CPC();
            CPW1();
        } else {
            CPW0();
        }
        __syncthreads();          // stage buf visible to all; also fences Q on iter 0

        const uint32_t stB = sbase + (OFF_ST0 + buf * STG_SZ) * 4;

        uint32_t aQh[4][4], aQl[4][4];
#pragma unroll
        for (int ks = 0; ks < 4; ks++) {
            uint32_t ad = sbase + arow * 144 + ks * 32 + acolB;
            LDMX4(aQh[ks], ad);
            LDMX4(aQl[ks], ad + ARQ * 4);
        }

        float S[8][4];
#pragma unroll
        for (int j = 0; j < 8; j++)
#pragma unroll
            for (int i = 0; i < 4; i++) S[j][i] = 0.0f;
#pragma unroll
        for (int j = 0; j < 8; j++) {
            uint32_t adh = stB + ((j * 8 + brow) * 36) * 4 + bcolB;
            uint32_t adl = adh + AR64 * 4;
            uint32_t kh[4], kl[4], kh2[4], kl2[4];
            LDMX4(kh, adh);
            LDMX4(kl, adl);
            LDMX4(kh2, adh + 64);
            LDMX4(kl2, adl + 64);
            mma16816(S[j], aQh[0], kh[0], kh[1]);
            mma16816(S[j], aQl[0], kh[0], kh[1]);
            mma16816(S[j], aQh[0], kl[0], kl[1]);
            mma16816(S[j], aQh[1], kh[2], kh[3]);
            mma16816(S[j], aQl[1], kh[2], kh[3]);
            mma16816(S[j], aQh[1], kl[2], kl[3]);
            mma16816(S[j], aQh[2], kh2[0], kh2[1]);
            mma16816(S[j], aQl[2], kh2[0], kh2[1]);
            mma16816(S[j], aQh[2], kl2[0], kl2[1]);
            mma16816(S[j], aQh[3], kh2[2], kh2[3]);
            mma16816(S[j], aQl[3], kh2[2], kh2[3]);
            mma16816(S[j], aQh[3], kl2[2], kl2[3]);
        }

        if (jt >= 2 * qt) {
            int qg0 = qt * 128 + qrow, qg1 = qg0 + 8;
            int kbse = jt * 64;
#pragma unroll
            for (int j = 0; j < 8; j++) {
                int kc = kbse + j * 8 + 2 * tt;
                if (kc     > qg0) S[j][0] = -1e30f;
                if (kc + 1 > qg0) S[j][1] = -1e30f;
                if (kc     > qg1) S[j][2] = -1e30f;
                if (kc + 1 > qg1) S[j][3] = -1e30f;
            }
        }

        float mx0 = -1e30f, mx1 = -1e30f;
#pragma unroll
        for (int j = 0; j < 8; j++) {
            mx0 = fmaxf(mx0, fmaxf(S[j][0], S[j][1]));
            mx1 = fmaxf(mx1, fmaxf(S[j][2], S[j][3]));
        }
        mx0 = fmaxf(mx0, __shfl_xor_sync(0xffffffff, mx0, 1));
        mx0 = fmaxf(mx0, __shfl_xor_sync(0xffffffff, mx0, 2));
        mx1 = fmaxf(mx1, __shfl_xor_sync(0xffffffff, mx1, 1));
        mx1 = fmaxf(mx1, __shfl_xor_sync(0xffffffff, mx1, 2));
        float mn0 = fmaxf(m0r, mx0), mn1 = fmaxf(m1r, mx1);
        float al0 = fexp2((m0r - mn0) * C2), al1 = fexp2((m1r - mn1) * C2);
        l0r *= al0; l1r *= al1;
#pragma unroll
        for (int j = 0; j < 8; j++) {
            O[j][0] *= al0; O[j][1] *= al0; O[j][2] *= al1; O[j][3] *= al1;
        }

        uint32_t ph[4][4], pl[4][4];
        float s0 = 0.0f, s1 = 0.0f;
#pragma unroll
        for (int j = 0; j < 8; j++) {
            float p0 = fexp2((S[j][0] - mn0) * C2);
            float p1 = fexp2((S[j][1] - mn0) * C2);
            float p2 = fexp2((S[j][2] - mn1) * C2);
            float p3 = fexp2((S[j][3] - mn1) * C2);
            s0 += p0 + p1; s1 += p2 + p3;
            uint32_t h01 = pack2bf(p0, p1);
            uint32_t l01 = pack2bf(p0 - lowf(h01), p1 - highf(h01));
            uint32_t h23 = pack2bf(p2, p3);
            uint32_t l23 = pack2bf(p2 - lowf(h23), p3 - highf(h23));
            int s = j >> 1;
            if (!(j & 1)) { ph[s][0] = h01; ph[s][1] = h23; pl[s][0] = l01; pl[s][1] = l23; }
            else          { ph[s][2] = h01; ph[s][3] = h23; pl[s][2] = l01; pl[s][3] = l23; }
        }
        s0 += __shfl_xor_sync(0xffffffff, s0, 1);
        s0 += __shfl_xor_sync(0xffffffff, s0, 2);
        s1 += __shfl_xor_sync(0xffffffff, s1, 1);
        s1 += __shfl_xor_sync(0xffffffff, s1, 2);
        l0r += s0; l1r += s1;
        m0r = mn0; m1r = mn1;

#pragma unroll
        for (int j = 0; j < 8; j++) {
            uint32_t adh = stB + (2*AR64 + (j * 8 + brow) * 36) * 4 + bcolB;
            uint32_t adl = adh + AR64 * 4;
            uint32_t vh[4], vl[4], vh2[4], vl2[4];
            LDMX4(vh, adh);
            LDMX4(vl, adl);
            LDMX4(vh2, adh + 64);
            LDMX4(vl2, adl + 64);
            mma16816(O[j], ph[0], vh[0], vh[1]);
            mma16816(O[j], pl[0], vh[0], vh[1]);
            mma16816(O[j], ph[0], vl[0], vl[1]);
            mma16816(O[j], ph[1], vh[2], vh[3]);
            mma16816(O[j], pl[1], vh[2], vh[3]);
            mma16816(O[j], ph[1], vl[2], vl[3]);
            mma16816(O[j], ph[2], vh2[0], vh2[1]);
            mma16816(O[j], pl[2], vh2[0], vh2[1]);
            mma16816(O[j], ph[2], vl2[0], vl2[1]);
            mma16816(O[j], ph[3], vh2[2], vh2[3]);
            mma16816(O[j], pl[3], vh2[2], vh2[3]);
            mma16816(O[j], ph[3], vl2[2], vl2[3]);
        }
        __syncthreads();          // compute(buf) done before stage buf re-issued at jt+2
    }

    const int slot = ((b * QT_N) + qt) * MAXC + chunk;
    float* po = g_po + (size_t)slot * 128 * 64;
#pragma unroll
    for (int j = 0; j < 8; j++) {
        *(float2*)&po[qrow * 64 + j * 8 + 2 * tt]       = make_float2(O[j][0], O[j][1]);
        *(float2*)&po[(qrow + 8) * 64 + j * 8 + 2 * tt] = make_float2(O[j][2], O[j][3]);
    }
    if (tt == 0) {
        g_pm[slot * 128 + qrow]     = m0r * 0.125f;
        g_pm[slot * 128 + qrow + 8] = m1r * 0.125f;
        g_pl[slot * 128 + qrow]     = l0r;
        g_pl[slot * 128 + qrow + 8] = l1r;
    }
}

// ------------------- combine: 512 blocks, 8 cols/thread -------------------
__global__ __launch_bounds__(256) void attn_combine_kernel(float* __restrict__ y)
{
    const int qt = blockIdx.x >> 2, quarter = blockIdx.x & 3, b = blockIdx.y;
    const int nc = min((2 * qt + 2 + CHUNK - 1) / CHUNK, MAXC);
    const int t = threadIdx.x;
    const int r = quarter * 32 + (t >> 3), c0 = (t & 7) * 8;
    const int base = ((b * QT_N) + qt) * MAXC;

    float M = -1e30f;
#pragma unroll 4
    for (int c = 0; c < nc; c++) M = fmaxf(M, g_pm[(base + c) * 128 + r]);
    float wgt[MAXC];
    float L = 0.0f;
#pragma unroll 4
    for (int c = 0; c < nc; c++) {
        wgt[c] = __expf(g_pm[(base + c) * 128 + r] - M);
        L += g_pl[(base + c) * 128 + r] * wgt[c];
    }
    const float inv = 1.0f / L;

    float acc[8];
#pragma unroll
    for (int k = 0; k < 8; k++) acc[k] = 0.0f;
    for (int c = 0; c < nc; c++) {
        const float* po = g_po + (size_t)(base + c) * 128 * 64 + r * 64 + c0;
        const float wc = wgt[c];
#pragma unroll
        for (int v = 0; v < 2; v++) {
            float4 p4 = *(const float4*)(po + v * 4);
            acc[v*4+0] = fmaf(p4.x, wc, acc[v*4+0]);
            acc[v*4+1] = fmaf(p4.y, wc, acc[v*4+1]);
            acc[v*4+2] = fmaf(p4.z, wc, acc[v*4+2]);
            acc[v*4+3] = fmaf(p4.w, wc, acc[v*4+3]);
        }
    }
    float* Y = y + ((size_t)b * Sn + qt * 128 + r) * Hn + c0;
#pragma unroll
    for (int v = 0; v < 2; v++) {
        *(float4*)(Y + v * 4) = make_float4(acc[v*4+0]*inv, acc[v*4+1]*inv,
                                            acc[v*4+2]*inv, acc[v*4+3]*inv);
    }
}

extern "C" void kernel_launch(void* const* d_in, const int* in_sizes, int n_in,
                              void* d_out, int out_size)
{
    const float* x  = (const float*)d_in[0];
    const float* wq = (const float*)d_in[1];
    const float* bq = (const float*)d_in[2];
    const float* wk = (const float*)d_in[3];
    const float* bk = (const float*)d_in[4];
    const float* wv = (const float*)d_in[5];
    const float* bv = (const float*)d_in[6];
    float* y = (float*)d_out;

    conv_w_kernel<<<(3 * Hn * En + 255) / 256, 256>>>(wq, wk, wv);

    cudaFuncSetAttribute(qkv_mma_kernel, cudaFuncAttributeMaxDynamicSharedMemorySize, QKV_SMEM);
    qkv_mma_kernel<<<Mn / 64, 128, QKV_SMEM>>>(x, bq, bk, bv);

    cudaFuncSetAttribute(attn_partial_kernel, cudaFuncAttributeMaxDynamicSharedMemorySize, ATT_SMEM);
    attn_partial_kernel<<<dim3(MAXC, QT_N, Bn), 256, ATT_SMEM>>>();

    attn_combine_kernel<<<dim3(4 * QT_N, Bn), 256>>>(y);
}

// round 14
// speedup vs baseline: 1.4982x; 1.0115x over previous
#include <cuda_runtime.h>
#include <cuda_bf16.h>
#include <cstdint>

#define Bn 8
#define Sn 2048
#define En 1024
#define Hn 64
#define Mn (Bn * Sn)
#define QT_N 16
#define CHUNK 8
#define MAXC 4

__device__ uint32_t g_qh[Mn * 32];
__device__ uint32_t g_ql[Mn * 32];
__device__ uint32_t g_kh[Mn * 32];
__device__ uint32_t g_kl[Mn * 32];
__device__ uint32_t g_vth[Bn * Hn * (Sn / 2)];
__device__ uint32_t g_vtl[Bn * Hn * (Sn / 2)];

__device__ float g_po[(size_t)Bn * QT_N * MAXC * 128 * 64];
__device__ float g_pm[Bn * QT_N * MAXC * 128];
__device__ float g_pl[Bn * QT_N * MAXC * 128];
__device__ __nv_bfloat16 g_wt[6 * 64 * En];

__device__ __forceinline__ uint32_t smem_u32(const void* p) {
    uint32_t a;
    asm("{ .reg .u64 t; cvta.to.shared.u64 t, %1; cvt.u32.u64 %0, t; }" : "=r"(a) : "l"(p));
    return a;
}
__device__ __forceinline__ void mma16816(float* c, const uint32_t* a,
                                         uint32_t b0, uint32_t b1) {
    asm volatile(
        "mma.sync.aligned.m16n8k16.row.col.f32.bf16.bf16.f32 "
        "{%0,%1,%2,%3}, {%4,%5,%6,%7}, {%8,%9}, {%0,%1,%2,%3};"
        : "+f"(c[0]), "+f"(c[1]), "+f"(c[2]), "+f"(c[3])
        : "r"(a[0]), "r"(a[1]), "r"(a[2]), "r"(a[3]), "r"(b0), "r"(b1));
}
#define LDMX4(r, ad) \
    asm volatile("ldmatrix.sync.aligned.m8n8.x4.shared.b16 {%0,%1,%2,%3}, [%4];" \
        : "=r"((r)[0]), "=r"((r)[1]), "=r"((r)[2]), "=r"((r)[3]) : "r"(ad))
#define CPA16(dst, src) asm volatile("cp.async.cg.shared.global [%0], [%1], 16;" :: "r"(dst), "l"(src))
#define CPC()  asm volatile("cp.async.commit_group;")
#define CPW1() asm volatile("cp.async.wait_group 1;" ::: "memory")
#define CPW0() asm volatile("cp.async.wait_group 0;" ::: "memory")

__device__ __forceinline__ uint32_t pack2bf(float f0, float f1) {
    __nv_bfloat16 b0 = __float2bfloat16(f0);
    __nv_bfloat16 b1 = __float2bfloat16(f1);
    return (uint32_t)__bfloat16_as_ushort(b0) | ((uint32_t)__bfloat16_as_ushort(b1) << 16);
}
__device__ __forceinline__ float lowf(uint32_t u)  { return __int_as_float(u << 16); }
__device__ __forceinline__ float highf(uint32_t u) { return __int_as_float(u & 0xFFFF0000u); }

// MUFU-pipe exp2 (offloads the softmax chain from FMA pipe)
__device__ __forceinline__ float fexp2(float x) {
    float r;
    asm("ex2.approx.ftz.f32 %0, %1;" : "=f"(r) : "f"(x));
    return r;
}
#define C2 0.1803368801111204f

// ------------------- conv_w -------------------
__global__ __launch_bounds__(256) void conv_w_kernel(
    const float* __restrict__ wq, const float* __restrict__ wk, const float* __restrict__ wv)
{
    const float* wsrc[3] = {wq, wk, wv};
    int id = blockIdx.x * 256 + threadIdx.x;
    if (id >= 3 * Hn * En) return;
    int mat = id / (Hn * En);
    int rem = id % (Hn * En);
    int n = rem / En, k = rem % En;
    float v = wsrc[mat][(size_t)k * Hn + n];
    __nv_bfloat16 hi = __float2bfloat16(v);
    __nv_bfloat16 lo = __float2bfloat16(v - __bfloat162float(hi));
    g_wt[((size_t)(mat * 2 + 0) * Hn + n) * En + k] = hi;
    g_wt[((size_t)(mat * 2 + 1) * Hn + n) * En + k] = lo;
}

// ------------------- qkv: cp.async double-buffered (round-12, passing) -------------------
#define KC 32
#define ALD 40
#define QS_AH 0
#define QS_AL 5120
#define QS_B  10240
#define QS_BSZ 30720
#define QKV_SMEM (QS_B + 2 * QS_BSZ)

__global__ __launch_bounds__(128) void qkv_mma_kernel(
    const float* __restrict__ x,
    const float* __restrict__ bq, const float* __restrict__ bk, const float* __restrict__ bv)
{
    extern __shared__ char qsm[];
    __nv_bfloat16* sAh = (__nv_bfloat16*)(qsm + QS_AH);
    __nv_bfloat16* sAl = (__nv_bfloat16*)(qsm + QS_AL);
    const uint32_t sb = smem_u32(qsm);
    const int t = threadIdx.x, w = t >> 5, lane = t & 31;
    const int g = lane >> 2, tt = lane & 3, m0 = blockIdx.x * 64;

    float acc[3][8][4];
#pragma unroll
    for (int m = 0; m < 3; m++)
#pragma unroll
        for (int n = 0; n < 8; n++)
#pragma unroll
            for (int i = 0; i < 4; i++) acc[m][n][i] = 0.0f;

    const int arow = w * 16 + (lane & 15);
    const int acol = (lane >> 4) << 3;
    const int brow = lane & 7;
    const int bcol = ((lane >> 3) & 3) << 3;

    const int xrow = t >> 1, xoff = (t & 1) * 16;
    const float* xbase = x + (size_t)(m0 + xrow) * En + xoff;

    float4 xr[4];
    xr[0] = *(const float4*)xbase;
    xr[1] = *(const float4*)(xbase + 4);
    xr[2] = *(const float4*)(xbase + 8);
    xr[3] = *(const float4*)(xbase + 12);
#pragma unroll
    for (int i = 0; i < 12; i++) {
        int idx = t + i * 128, row = idx >> 2, q = idx & 3;
        CPA16(sb + QS_B + row * 80 + q * 16,
              (const char*)(g_wt + (size_t)row * En) + q * 16);
    }
    CPC();

    for (int c = 0; c < 32; c++) {
        const int buf = c & 1;
        __syncthreads();

        {
            float f[16];
            f[0]=xr[0].x; f[1]=xr[0].y; f[2]=xr[0].z; f[3]=xr[0].w;
            f[4]=xr[1].x; f[5]=xr[1].y; f[6]=xr[1].z; f[7]=xr[1].w;
            f[8]=xr[2].x; f[9]=xr[2].y; f[10]=xr[2].z; f[11]=xr[2].w;
            f[12]=xr[3].x; f[13]=xr[3].y; f[14]=xr[3].z; f[15]=xr[3].w;
            uint32_t hi[8], lo[8];
#pragma unroll
            for (int j = 0; j < 8; j++) {
                hi[j] = pack2bf(f[2*j], f[2*j+1]);
                lo[j] = pack2bf(f[2*j] - lowf(hi[j]), f[2*j+1] - highf(hi[j]));
            }
            uint32_t eo = (uint32_t)(xrow * ALD + xoff);
            *(uint4*)&sAh[eo]     = make_uint4(hi[0], hi[1], hi[2], hi[3]);
            *(uint4*)&sAh[eo + 8] = make_uint4(hi[4], hi[5], hi[6], hi[7]);
            *(uint4*)&sAl[eo]     = make_uint4(lo[0], lo[1], lo[2], lo[3]);
            *(uint4*)&sAl[eo + 8] = make_uint4(lo[4], lo[5], lo[6], lo[7]);
        }

        if (c < 31) {
            const int k1 = (c + 1) * KC;
#pragma unroll
            for (int i = 0; i < 12; i++) {
                int idx = t + i * 128, row = idx >> 2, q = idx & 3;
                CPA16(sb + QS_B + (buf ^ 1) * QS_BSZ + row * 80 + q * 16,
                      (const char*)(g_wt + (size_t)row * En + k1) + q * 16);
            }
            CPC();
            const float* xp = xbase + k1;
            xr[0] = *(const float4*)xp;
            xr[1] = *(const float4*)(xp + 4);
            xr[2] = *(const float4*)(xp + 8);
            xr[3] = *(const float4*)(xp + 12);
            CPW1();
        } else {
            CPW0();
        }
        __syncthreads();

        const uint32_t bbase = sb + QS_B + buf * QS_BSZ;
        uint32_t aH[2][4], aL[2][4];
#pragma unroll
        for (int ks = 0; ks < 2; ks++) {
            uint32_t ad = sb + QS_AH + (arow * ALD + ks * 16 + acol) * 2;
            LDMX4(aH[ks], ad);
            LDMX4(aL[ks], ad + QS_AL);
        }
#pragma unroll
        for (int mat = 0; mat < 3; mat++) {
#pragma unroll
            for (int n8 = 0; n8 < 8; n8++) {
                uint32_t bh[4], bl[4];
                LDMX4(bh, bbase + (((mat*2+0)*64 + n8*8 + brow) * ALD + bcol) * 2);
                LDMX4(bl, bbase + (((mat*2+1)*64 + n8*8 + brow) * ALD + bcol) * 2);
                mma16816(acc[mat][n8], aH[0], bh[0], bh[1]);
                mma16816(acc[mat][n8], aL[0], bh[0], bh[1]);
                mma16816(acc[mat][n8], aH[0], bl[0], bl[1]);
                mma16816(acc[mat][n8], aH[1], bh[2], bh[3]);
                mma16816(acc[mat][n8], aL[1], bh[2], bh[3]);
                mma16816(acc[mat][n8], aH[1], bl[2], bl[3]);
            }
        }
    }

    const int rl = w * 16 + g;
    {
        uint32_t* gh2[2] = {g_qh, g_kh};
        uint32_t* gl2[2] = {g_ql, g_kl};
        const float* bias2[2] = {bq, bk};
#pragma unroll
        for (int mat = 0; mat < 2; mat++) {
#pragma unroll
            for (int n8 = 0; n8 < 8; n8++) {
                int col = n8 * 8 + 2 * tt;
                float b0 = __ldg(bias2[mat] + col), b1 = __ldg(bias2[mat] + col + 1);
                float v00 = acc[mat][n8][0] + b0, v01 = acc[mat][n8][1] + b1;
                float v10 = acc[mat][n8][2] + b0, v11 = acc[mat][n8][3] + b1;
                uint32_t hA = pack2bf(v00, v01);
                uint32_t lA = pack2bf(v00 - lowf(hA), v01 - highf(hA));
                uint32_t hB = pack2bf(v10, v11);
                uint32_t lB = pack2bf(v10 - lowf(hB), v11 - highf(hB));
                size_t iA = (size_t)(m0 + rl) * 32 + n8 * 4 + tt;
                size_t iB = (size_t)(m0 + rl + 8) * 32 + n8 * 4 + tt;
                gh2[mat][iA] = hA; gl2[mat][iA] = lA;
                gh2[mat][iB] = hB; gl2[mat][iB] = lB;
            }
        }
    }
    float* vsm = (float*)(qsm + QS_B);
    __syncthreads();
#pragma unroll
    for (int n8 = 0; n8 < 8; n8++) {
        int col = n8 * 8 + 2 * tt;
        float b0 = __ldg(bv + col), b1 = __ldg(bv + col + 1);
        vsm[rl * 66 + col]           = acc[2][n8][0] + b0;
        vsm[rl * 66 + col + 1]       = acc[2][n8][1] + b1;
        vsm[(rl + 8) * 66 + col]     = acc[2][n8][2] + b0;
        vsm[(rl + 8) * 66 + col + 1] = acc[2][n8][3] + b1;
    }
    __syncthreads();
    {
        int h = t >> 1, half = t & 1;
        int bb = m0 >> 11;
        int sp0 = ((m0 & 2047) + half * 32) >> 1;
        uint32_t oh[16], ol[16];
#pragma unroll
        for (int s = 0; s < 16; s++) {
            float a = vsm[(half * 32 + 2 * s) * 66 + h];
            float cc = vsm[(half * 32 + 2 * s + 1) * 66 + h];
            oh[s] = pack2bf(a, cc);
            ol[s] = pack2bf(a - lowf(oh[s]), cc - highf(oh[s]));
        }
        uint32_t* gvh = g_vth + (size_t)(bb * Hn + h) * (Sn / 2) + sp0;
        uint32_t* gvl = g_vtl + (size_t)(bb * Hn + h) * (Sn / 2) + sp0;
#pragma unroll
        for (int q = 0; q < 4; q++) {
            *(uint4*)(gvh + q * 4) = make_uint4(oh[q*4], oh[q*4+1], oh[q*4+2], oh[q*4+3]);
            *(uint4*)(gvl + q * 4) = make_uint4(ol[q*4], ol[q*4+1], ol[q*4+2], ol[q*4+3]);
        }
    }
}

// ------------------- attention partials: CHUNK=8, double-buffered KV -------------------
#define AR64 2304
#define ARQ  4608
#define OFF_ST0 (2*ARQ)
#define STG_SZ  (4*AR64)
#define ATT_SMEM ((2*ARQ + 2*STG_SZ) * 4)

__global__ __launch_bounds__(256, 2) void attn_partial_kernel()
{
    const int chunk = blockIdx.x, qt = blockIdx.y, b = blockIdx.z;
    const int nt = 2 * qt + 2;
    const int jt0 = chunk * CHUNK;
    if (jt0 >= nt) return;
    const int jt1 = min(jt0 + CHUNK, nt);

    extern __shared__ uint32_t su[];
    const uint32_t sbase = smem_u32(su);
    const int t = threadIdx.x, w = t >> 5, lane = t & 31;
    const int g = lane >> 2, tt = lane & 3;
    const int qrow = w * 16 + g;

    const int arow = w * 16 + (lane & 15);
    const int acolB = ((lane >> 4) << 3) * 2;
    const int brow = lane & 7;
    const int bcolB = (((lane >> 3) & 3) << 3) * 2;

    {
        const uint4* qh4 = (const uint4*)g_qh;
        const uint4* ql4 = (const uint4*)g_ql;
        size_t gb = ((size_t)b * Sn + qt * 128) * 8;
#pragma unroll
        for (int i = 0; i < 4; i++) {
            int u = t + i * 256, r = u >> 3, c = u & 7;
            *(uint4*)&su[r * 36 + c * 4]       = qh4[gb + r * 8 + c];
            *(uint4*)&su[ARQ + r * 36 + c * 4] = ql4[gb + r * 8 + c];
        }
    }

    const int sr = t >> 3, scc = t & 7;
    {
        size_t kb = ((size_t)b * Sn + jt0 * 64) * 8;
#pragma unroll
        for (int i = 0; i < 2; i++) {
            int r = sr + i * 32;
            uint32_t dst = sbase + (OFF_ST0 + r * 36 + scc * 4) * 4;
            CPA16(dst,               (const char*)((const uint4*)g_kh + kb + r * 8 + scc));
            CPA16(dst + AR64 * 4,    (const char*)((const uint4*)g_kl + kb + r * 8 + scc));
            size_t vb = (size_t)(b * Hn + r) * 256 + jt0 * 8 + scc;
            CPA16(dst + 2*AR64 * 4,  (const char*)((const uint4*)g_vth + vb));
            CPA16(dst + 3*AR64 * 4,  (const char*)((const uint4*)g_vtl + vb));
        }
        CPC();
    }

    float m0r = -1e30f, m1r = -1e30f, l0r = 0.0f, l1r = 0.0f;
    float O[8][4];
#pragma unroll
    for (int j = 0; j < 8; j++)
#pragma unroll
        for (int i = 0; i < 4; i++) O[j][i] = 0.0f;

    for (int jt = jt0; jt < jt1; jt++) {
        const int buf = (jt - jt0) & 1;
        if (jt + 1 < jt1) {
            size_t kb = ((size_t)b * Sn + (jt + 1) * 64) * 8;
            uint32_t stb = OFF_ST0 + (buf ^ 1) * STG_SZ;
#pragma unroll
            for (int i = 0; i < 2; i++) {
                int r = sr + i * 32;
                uint32_t dst = sbase + (stb + r * 36 + scc * 4) * 4;
                CPA16(dst,              (const char*)((const uint4*)g_kh + kb + r * 8 + scc));
                CPA16(dst + AR64 * 4,   (const char*)((const uint4*)g_kl + kb + r * 8 + scc));
                size_t vb = (size_t)(b * Hn + r) * 256 + (jt + 1) * 8 + scc;
                CPA16(dst + 2*AR64 * 4, (const char*)((const uint4*)g_vth + vb));
                CPA16(dst + 3*AR64 * 4, (const char*)((const uint4*)g_vtl + vb));
            }
            CPC();
            CPW1();
        } else {
            CPW0();
        }
        __syncthreads();

        const uint32_t stB = sbase + (OFF_ST0 + buf * STG_SZ) * 4;

        uint32_t aQh[4][4], aQl[4][4];
#pragma unroll
        for (int ks = 0; ks < 4; ks++) {
            uint32_t ad = sbase + arow * 144 + ks * 32 + acolB;
            LDMX4(aQh[ks], ad);
            LDMX4(aQl[ks], ad + ARQ * 4);
        }

        float S[8][4];
#pragma unroll
        for (int j = 0; j < 8; j++)
#pragma unroll
            for (int i = 0; i < 4; i++) S[j][i] = 0.0f;
#pragma unroll
        for (int j = 0; j < 8; j++) {
            uint32_t adh = stB + ((j * 8 + brow) * 36) * 4 + bcolB;
            uint32_t adl = adh + AR64 * 4;
            uint32_t kh[4], kl[4], kh2[4], kl2[4];
            LDMX4(kh, adh);
            LDMX4(kl, adl);
            LDMX4(kh2, adh + 64);
            LDMX4(kl2, adl + 64);
            mma16816(S[j], aQh[0], kh[0], kh[1]);
            mma16816(S[j], aQl[0], kh[0], kh[1]);
            mma16816(S[j], aQh[0], kl[0], kl[1]);
            mma16816(S[j], aQh[1], kh[2], kh[3]);
            mma16816(S[j], aQl[1], kh[2], kh[3]);
            mma16816(S[j], aQh[1], kl[2], kl[3]);
            mma16816(S[j], aQh[2], kh2[0], kh2[1]);
            mma16816(S[j], aQl[2], kh2[0], kh2[1]);
            mma16816(S[j], aQh[2], kl2[0], kl2[1]);
            mma16816(S[j], aQh[3], kh2[2], kh2[3]);
            mma16816(S[j], aQl[3], kh2[2], kh2[3]);
            mma16816(S[j], aQh[3], kl2[2], kl2[3]);
        }

        if (jt >= 2 * qt) {
            int qg0 = qt * 128 + qrow, qg1 = qg0 + 8;
            int kbse = jt * 64;
#pragma unroll
            for (int j = 0; j < 8; j++) {
                int kc = kbse + j * 8 + 2 * tt;
                if (kc     > qg0) S[j][0] = -1e30f;
                if (kc + 1 > qg0) S[j][1] = -1e30f;
                if (kc     > qg1) S[j][2] = -1e30f;
                if (kc + 1 > qg1) S[j][3] = -1e30f;
            }
        }

        float mx0 = -1e30f, mx1 = -1e30f;
#pragma unroll
        for (int j = 0; j < 8; j++) {
            mx0 = fmaxf(mx0, fmaxf(S[j][0], S[j][1]));
            mx1 = fmaxf(mx1, fmaxf(S[j][2], S[j][3]));
        }
        mx0 = fmaxf(mx0, __shfl_xor_sync(0xffffffff, mx0, 1));
        mx0 = fmaxf(mx0, __shfl_xor_sync(0xffffffff, mx0, 2));
        mx1 = fmaxf(mx1, __shfl_xor_sync(0xffffffff, mx1, 1));
        mx1 = fmaxf(mx1, __shfl_xor_sync(0xffffffff, mx1, 2));
        float mn0 = fmaxf(m0r, mx0), mn1 = fmaxf(m1r, mx1);
        float al0 = fexp2((m0r - mn0) * C2), al1 = fexp2((m1r - mn1) * C2);
        l0r *= al0; l1r *= al1;
#pragma unroll
        for (int j = 0; j < 8; j++) {
            O[j][0] *= al0; O[j][1] *= al0; O[j][2] *= al1; O[j][3] *= al1;
        }

        uint32_t ph[4][4], pl[4][4];
        float s0 = 0.0f, s1 = 0.0f;
#pragma unroll
        for (int j = 0; j < 8; j++) {
            float p0 = fexp2((S[j][0] - mn0) * C2);
            float p1 = fexp2((S[j][1] - mn0) * C2);
            float p2 = fexp2((S[j][2] - mn1) * C2);
            float p3 = fexp2((S[j][3] - mn1) * C2);
            s0 += p0 + p1; s1 += p2 + p3;
            uint32_t h01 = pack2bf(p0, p1);
            uint32_t l01 = pack2bf(p0 - lowf(h01), p1 - highf(h01));
            uint32_t h23 = pack2bf(p2, p3);
            uint32_t l23 = pack2bf(p2 - lowf(h23), p3 - highf(h23));
            int s = j >> 1;
            if (!(j & 1)) { ph[s][0] = h01; ph[s][1] = h23; pl[s][0] = l01; pl[s][1] = l23; }
            else          { ph[s][2] = h01; ph[s][3] = h23; pl[s][2] = l01; pl[s][3] = l23; }
        }
        s0 += __shfl_xor_sync(0xffffffff, s0, 1);
        s0 += __shfl_xor_sync(0xffffffff, s0, 2);
        s1 += __shfl_xor_sync(0xffffffff, s1, 1);
        s1 += __shfl_xor_sync(0xffffffff, s1, 2);
        l0r += s0; l1r += s1;
        m0r = mn0; m1r = mn1;

#pragma unroll
        for (int j = 0; j < 8; j++) {
            uint32_t adh = stB + (2*AR64 + (j * 8 + brow) * 36) * 4 + bcolB;
            uint32_t adl = adh + AR64 * 4;
            uint32_t vh[4], vl[4], vh2[4], vl2[4];
            LDMX4(vh, adh);
            LDMX4(vl, adl);
            LDMX4(vh2, adh + 64);
            LDMX4(vl2, adl + 64);
            mma16816(O[j], ph[0], vh[0], vh[1]);
            mma16816(O[j], pl[0], vh[0], vh[1]);
            mma16816(O[j], ph[0], vl[0], vl[1]);
            mma16816(O[j], ph[1], vh[2], vh[3]);
            mma16816(O[j], pl[1], vh[2], vh[3]);
            mma16816(O[j], ph[1], vl[2], vl[3]);
            mma16816(O[j], ph[2], vh2[0], vh2[1]);
            mma16816(O[j], pl[2], vh2[0], vh2[1]);
            mma16816(O[j], ph[2], vl2[0], vl2[1]);
            mma16816(O[j], ph[3], vh2[2], vh2[3]);
            mma16816(O[j], pl[3], vh2[2], vh2[3]);
            mma16816(O[j], ph[3], vl2[2], vl2[3]);
        }
        __syncthreads();
    }

    const int slot = ((b * QT_N) + qt) * MAXC + chunk;
    float* po = g_po + (size_t)slot * 128 * 64;
#pragma unroll
    for (int j = 0; j < 8; j++) {
        *(float2*)&po[qrow * 64 + j * 8 + 2 * tt]       = make_float2(O[j][0], O[j][1]);
        *(float2*)&po[(qrow + 8) * 64 + j * 8 + 2 * tt] = make_float2(O[j][2], O[j][3]);
    }
    if (tt == 0) {
        g_pm[slot * 128 + qrow]     = m0r * 0.125f;
        g_pm[slot * 128 + qrow + 8] = m1r * 0.125f;
        g_pl[slot * 128 + qrow]     = l0r;
        g_pl[slot * 128 + qrow + 8] = l1r;
    }
}

// ------------------- combine -------------------
__global__ __launch_bounds__(256) void attn_combine_kernel(float* __restrict__ y)
{
    const int qt = blockIdx.x >> 2, quarter = blockIdx.x & 3, b = blockIdx.y;
    const int nc = min((2 * qt + 2 + CHUNK - 1) / CHUNK, MAXC);
    const int t = threadIdx.x;
    const int r = quarter * 32 + (t >> 3), c0 = (t & 7) * 8;
    const int base = ((b * QT_N) + qt) * MAXC;

    float M = -1e30f;
#pragma unroll
    for (int c = 0; c < MAXC; c++)
        if (c < nc) M = fmaxf(M, g_pm[(base + c) * 128 + r]);
    float wgt[MAXC];
    float L = 0.0f;
#pragma unroll
    for (int c = 0; c < MAXC; c++)
        if (c < nc) {
            wgt[c] = __expf(g_pm[(base + c) * 128 + r] - M);
            L += g_pl[(base + c) * 128 + r] * wgt[c];
        }
    const float inv = 1.0f / L;

    float acc[8];
#pragma unroll
    for (int k = 0; k < 8; k++) acc[k] = 0.0f;
    for (int c = 0; c < nc; c++) {
        const float* po = g_po + (size_t)(base + c) * 128 * 64 + r * 64 + c0;
        const float wc = wgt[c];
#pragma unroll
        for (int v = 0; v < 2; v++) {
            float4 p4 = *(const float4*)(po + v * 4);
            acc[v*4+0] = fmaf(p4.x, wc, acc[v*4+0]);
            acc[v*4+1] = fmaf(p4.y, wc, acc[v*4+1]);
            acc[v*4+2] = fmaf(p4.z, wc, acc[v*4+2]);
            acc[v*4+3] = fmaf(p4.w, wc, acc[v*4+3]);
        }
    }
    float* Y = y + ((size_t)b * Sn + qt * 128 + r) * Hn + c0;
#pragma unroll
    for (int v = 0; v < 2; v++) {
        *(float4*)(Y + v * 4) = make_float4(acc[v*4+0]*inv, acc[v*4+1]*inv,
                                            acc[v*4+2]*inv, acc[v*4+3]*inv);
    }
}

extern "C" void kernel_launch(void* const* d_in, const int* in_sizes, int n_in,
                              void* d_out, int out_size)
{
    const float* x  = (const float*)d_in[0];
    const float* wq = (const float*)d_in[1];
    const float* bq = (const float*)d_in[2];
    const float* wk = (const float*)d_in[3];
    const float* bk = (const float*)d_in[4];
    const float* wv = (const float*)d_in[5];
    const float* bv = (const float*)d_in[6];
    float* y = (float*)d_out;

    conv_w_kernel<<<(3 * Hn * En + 255) / 256, 256>>>(wq, wk, wv);

    cudaFuncSetAttribute(qkv_mma_kernel, cudaFuncAttributeMaxDynamicSharedMemorySize, QKV_SMEM);
    qkv_mma_kernel<<<Mn / 64, 128, QKV_SMEM>>>(x, bq, bk, bv);

    cudaFuncSetAttribute(attn_partial_kernel, cudaFuncAttributeMaxDynamicSharedMemorySize, ATT_SMEM);
    attn_partial_kernel<<<dim3(MAXC, QT_N, Bn), 256, ATT_SMEM>>>();

    attn_combine_kernel<<<dim3(4 * QT_N, Bn), 256>>>(y);
}

// round 15
// speedup vs baseline: 1.6438x; 1.0972x over previous
#include <cuda_runtime.h>
#include <cuda_bf16.h>
#include <cstdint>

#define Bn 8
#define Sn 2048
#define En 1024
#define Hn 64
#define Mn (Bn * Sn)
#define QT_N 16
#define CHUNK 8
#define MAXC 4

__device__ uint32_t g_qh[Mn * 32];
__device__ uint32_t g_ql[Mn * 32];
__device__ uint32_t g_kh[Mn * 32];
__device__ uint32_t g_kl[Mn * 32];
__device__ uint32_t g_vth[Bn * Hn * (Sn / 2)];
__device__ uint32_t g_vtl[Bn * Hn * (Sn / 2)];

__device__ float g_po[(size_t)Bn * QT_N * MAXC * 128 * 64];
__device__ float g_pm[Bn * QT_N * MAXC * 128];
__device__ float g_pl[Bn * QT_N * MAXC * 128];
__device__ __nv_bfloat16 g_wt[6 * 64 * En];

__device__ __forceinline__ uint32_t smem_u32(const void* p) {
    uint32_t a;
    asm("{ .reg .u64 t; cvta.to.shared.u64 t, %1; cvt.u32.u64 %0, t; }" : "=r"(a) : "l"(p));
    return a;
}
__device__ __forceinline__ void mma16816(float* c, const uint32_t* a,
                                         uint32_t b0, uint32_t b1) {
    asm volatile(
        "mma.sync.aligned.m16n8k16.row.col.f32.bf16.bf16.f32 "
        "{%0,%1,%2,%3}, {%4,%5,%6,%7}, {%8,%9}, {%0,%1,%2,%3};"
        : "+f"(c[0]), "+f"(c[1]), "+f"(c[2]), "+f"(c[3])
        : "r"(a[0]), "r"(a[1]), "r"(a[2]), "r"(a[3]), "r"(b0), "r"(b1));
}
#define LDMX4(r, ad) \
    asm volatile("ldmatrix.sync.aligned.m8n8.x4.shared.b16 {%0,%1,%2,%3}, [%4];" \
        : "=r"((r)[0]), "=r"((r)[1]), "=r"((r)[2]), "=r"((r)[3]) : "r"(ad))
#define CPA16(dst, src) asm volatile("cp.async.cg.shared.global [%0], [%1], 16;" :: "r"(dst), "l"(src))
#define CPC()  asm volatile("cp.async.commit_group;")
#define CPW1() asm volatile("cp.async.wait_group 1;" ::: "memory")
#define CPW0() asm volatile("cp.async.wait_group 0;" ::: "memory")

__device__ __forceinline__ uint32_t pack2bf(float f0, float f1) {
    __nv_bfloat16 b0 = __float2bfloat16(f0);
    __nv_bfloat16 b1 = __float2bfloat16(f1);
    return (uint32_t)__bfloat16_as_ushort(b0) | ((uint32_t)__bfloat16_as_ushort(b1) << 16);
}
__device__ __forceinline__ float lowf(uint32_t u)  { return __int_as_float(u << 16); }
__device__ __forceinline__ float highf(uint32_t u) { return __int_as_float(u & 0xFFFF0000u); }

__device__ __forceinline__ float fexp2(float x) {
    float r;
    asm("ex2.approx.ftz.f32 %0, %1;" : "=f"(r) : "f"(x));
    return r;
}
#define C2 0.1803368801111204f

// ------------------- conv_w -------------------
__global__ __launch_bounds__(256) void conv_w_kernel(
    const float* __restrict__ wq, const float* __restrict__ wk, const float* __restrict__ wv)
{
    const float* wsrc[3] = {wq, wk, wv};
    int id = blockIdx.x * 256 + threadIdx.x;
    if (id >= 3 * Hn * En) return;
    int mat = id / (Hn * En);
    int rem = id % (Hn * En);
    int n = rem / En, k = rem % En;
    float v = wsrc[mat][(size_t)k * Hn + n];
    __nv_bfloat16 hi = __float2bfloat16(v);
    __nv_bfloat16 lo = __float2bfloat16(v - __bfloat162float(hi));
    g_wt[((size_t)(mat * 2 + 0) * Hn + n) * En + k] = hi;
    g_wt[((size_t)(mat * 2 + 1) * Hn + n) * En + k] = lo;
}

// ------------------- qkv: 256 thr, 8 warps (N-split), cp.async 2-stage -------------------
#define KC 32
#define ALD 40
#define QS_AH 0
#define QS_AL 5120
#define QS_B  10240
#define QS_BSZ 30720
#define QKV_SMEM (QS_B + 2 * QS_BSZ)

__global__ __launch_bounds__(256, 2) void qkv_mma_kernel(
    const float* __restrict__ x,
    const float* __restrict__ bq, const float* __restrict__ bk, const float* __restrict__ bv)
{
    extern __shared__ char qsm[];
    __nv_bfloat16* sAh = (__nv_bfloat16*)(qsm + QS_AH);
    __nv_bfloat16* sAl = (__nv_bfloat16*)(qsm + QS_AL);
    const uint32_t sb = smem_u32(qsm);
    const int t = threadIdx.x, w = t >> 5, lane = t & 31;
    const int g = lane >> 2, tt = lane & 3, m0 = blockIdx.x * 64;
    const int wm = w & 3, nh = w >> 2;          // row-group, n-half

    float acc[3][4][4];
#pragma unroll
    for (int m = 0; m < 3; m++)
#pragma unroll
        for (int n = 0; n < 4; n++)
#pragma unroll
            for (int i = 0; i < 4; i++) acc[m][n][i] = 0.0f;

    const int arow = wm * 16 + (lane & 15);
    const int acol = (lane >> 4) << 3;
    const int brow = lane & 7;
    const int bcol = ((lane >> 3) & 3) << 3;

    // x staging: thread -> row t>>2 (0..63), 8 floats at (t&3)*8
    const int xrow = t >> 2, xoff = (t & 3) * 8;
    const float* xbase = x + (size_t)(m0 + xrow) * En + xoff;

    float4 xr[2];
    xr[0] = *(const float4*)xbase;
    xr[1] = *(const float4*)(xbase + 4);
#pragma unroll
    for (int i = 0; i < 6; i++) {
        int idx = t + i * 256, row = idx >> 2, q = idx & 3;
        CPA16(sb + QS_B + row * 80 + q * 16,
              (const char*)(g_wt + (size_t)row * En) + q * 16);
    }
    CPC();

    for (int c = 0; c < 32; c++) {
        const int buf = c & 1;
        __syncthreads();

        // convert xr(c) -> A smem (8 floats -> 1 uint4 hi + 1 uint4 lo)
        {
            float f[8] = {xr[0].x, xr[0].y, xr[0].z, xr[0].w,
                          xr[1].x, xr[1].y, xr[1].z, xr[1].w};
            uint32_t hi[4], lo[4];
#pragma unroll
            for (int j = 0; j < 4; j++) {
                hi[j] = pack2bf(f[2*j], f[2*j+1]);
                lo[j] = pack2bf(f[2*j] - lowf(hi[j]), f[2*j+1] - highf(hi[j]));
            }
            uint32_t eo = (uint32_t)(xrow * ALD + xoff);
            *(uint4*)&sAh[eo] = make_uint4(hi[0], hi[1], hi[2], hi[3]);
            *(uint4*)&sAl[eo] = make_uint4(lo[0], lo[1], lo[2], lo[3]);
        }

        if (c < 31) {
            const int k1 = (c + 1) * KC;
#pragma unroll
            for (int i = 0; i < 6; i++) {
                int idx = t + i * 256, row = idx >> 2, q = idx & 3;
                CPA16(sb + QS_B + (buf ^ 1) * QS_BSZ + row * 80 + q * 16,
                      (const char*)(g_wt + (size_t)row * En + k1) + q * 16);
            }
            CPC();
            const float* xp = xbase + k1;
            xr[0] = *(const float4*)xp;
            xr[1] = *(const float4*)(xp + 4);
            CPW1();
        } else {
            CPW0();
        }
        __syncthreads();

        const uint32_t bbase = sb + QS_B + buf * QS_BSZ;
        uint32_t aH[2][4], aL[2][4];
#pragma unroll
        for (int ks = 0; ks < 2; ks++) {
            uint32_t ad = sb + QS_AH + (arow * ALD + ks * 16 + acol) * 2;
            LDMX4(aH[ks], ad);
            LDMX4(aL[ks], ad + QS_AL);
        }
#pragma unroll
        for (int mat = 0; mat < 3; mat++) {
#pragma unroll
            for (int n8l = 0; n8l < 4; n8l++) {
                const int n8 = nh * 4 + n8l;
                uint32_t bh[4], bl[4];
                LDMX4(bh, bbase + (((mat*2+0)*64 + n8*8 + brow) * ALD + bcol) * 2);
                LDMX4(bl, bbase + (((mat*2+1)*64 + n8*8 + brow) * ALD + bcol) * 2);
                mma16816(acc[mat][n8l], aH[0], bh[0], bh[1]);
                mma16816(acc[mat][n8l], aL[0], bh[0], bh[1]);
                mma16816(acc[mat][n8l], aH[0], bl[0], bl[1]);
                mma16816(acc[mat][n8l], aH[1], bh[2], bh[3]);
                mma16816(acc[mat][n8l], aL[1], bh[2], bh[3]);
                mma16816(acc[mat][n8l], aH[1], bl[2], bl[3]);
            }
        }
    }

    // ---- epilogue: Q,K packed hi/lo ----
    const int rl = wm * 16 + g;
    {
        uint32_t* gh2[2] = {g_qh, g_kh};
        uint32_t* gl2[2] = {g_ql, g_kl};
        const float* bias2[2] = {bq, bk};
#pragma unroll
        for (int mat = 0; mat < 2; mat++) {
#pragma unroll
            for (int n8l = 0; n8l < 4; n8l++) {
                const int n8 = nh * 4 + n8l;
                int col = n8 * 8 + 2 * tt;
                float b0 = __ldg(bias2[mat] + col), b1 = __ldg(bias2[mat] + col + 1);
                float v00 = acc[mat][n8l][0] + b0, v01 = acc[mat][n8l][1] + b1;
                float v10 = acc[mat][n8l][2] + b0, v11 = acc[mat][n8l][3] + b1;
                uint32_t hA = pack2bf(v00, v01);
                uint32_t lA = pack2bf(v00 - lowf(hA), v01 - highf(hA));
                uint32_t hB = pack2bf(v10, v11);
                uint32_t lB = pack2bf(v10 - lowf(hB), v11 - highf(hB));
                size_t iA = (size_t)(m0 + rl) * 32 + n8 * 4 + tt;
                size_t iB = (size_t)(m0 + rl + 8) * 32 + n8 * 4 + tt;
                gh2[mat][iA] = hA; gl2[mat][iA] = lA;
                gh2[mat][iB] = hB; gl2[mat][iB] = lB;
            }
        }
    }
    // ---- epilogue: V transpose via smem ----
    float* vsm = (float*)(qsm + QS_B);      // [64][66] fp32
    __syncthreads();
#pragma unroll
    for (int n8l = 0; n8l < 4; n8l++) {
        const int n8 = nh * 4 + n8l;
        int col = n8 * 8 + 2 * tt;
        float b0 = __ldg(bv + col), b1 = __ldg(bv + col + 1);
        vsm[rl * 66 + col]           = acc[2][n8l][0] + b0;
        vsm[rl * 66 + col + 1]       = acc[2][n8l][1] + b1;
        vsm[(rl + 8) * 66 + col]     = acc[2][n8l][2] + b0;
        vsm[(rl + 8) * 66 + col + 1] = acc[2][n8l][3] + b1;
    }
    __syncthreads();
    {
        int h = t >> 2, qtr = t & 3;            // h 0..63, 16 seq rows per thread
        int bb = m0 >> 11;
        int sp0 = ((m0 & 2047) + qtr * 16) >> 1;
        uint32_t oh[8], ol[8];
#pragma unroll
        for (int s = 0; s < 8; s++) {
            float a  = vsm[(qtr * 16 + 2 * s) * 66 + h];
            float cc = vsm[(qtr * 16 + 2 * s + 1) * 66 + h];
            oh[s] = pack2bf(a, cc);
            ol[s] = pack2bf(a - lowf(oh[s]), cc - highf(oh[s]));
        }
        uint32_t* gvh = g_vth + (size_t)(bb * Hn + h) * (Sn / 2) + sp0;
        uint32_t* gvl = g_vtl + (size_t)(bb * Hn + h) * (Sn / 2) + sp0;
#pragma unroll
        for (int q = 0; q < 2; q++) {
            *(uint4*)(gvh + q * 4) = make_uint4(oh[q*4], oh[q*4+1], oh[q*4+2], oh[q*4+3]);
            *(uint4*)(gvl + q * 4) = make_uint4(ol[q*4], ol[q*4+1], ol[q*4+2], ol[q*4+3]);
        }
    }
}

// ------------------- attention partials: CHUNK=8, double-buffered KV (round-14) -------------------
#define AR64 2304
#define ARQ  4608
#define OFF_ST0 (2*ARQ)
#define STG_SZ  (4*AR64)
#define ATT_SMEM ((2*ARQ + 2*STG_SZ) * 4)

__global__ __launch_bounds__(256, 2) void attn_partial_kernel()
{
    const int chunk = blockIdx.x, qt = blockIdx.y, b = blockIdx.z;
    const int nt = 2 * qt + 2;
    const int jt0 = chunk * CHUNK;
    if (jt0 >= nt) return;
    const int jt1 = min(jt0 + CHUNK, nt);

    extern __shared__ uint32_t su[];
    const uint32_t sbase = smem_u32(su);
    const int t = threadIdx.x, w = t >> 5, lane = t & 31;
    const int g = lane >> 2, tt = lane & 3;
    const int qrow = w * 16 + g;

    const int arow = w * 16 + (lane & 15);
    const int acolB = ((lane >> 4) << 3) * 2;
    const int brow = lane & 7;
    const int bcolB = (((lane >> 3) & 3) << 3) * 2;

    {
        const uint4* qh4 = (const uint4*)g_qh;
        const uint4* ql4 = (const uint4*)g_ql;
        size_t gb = ((size_t)b * Sn + qt * 128) * 8;
#pragma unroll
        for (int i = 0; i < 4; i++) {
            int u = t + i * 256, r = u >> 3, c = u & 7;
            *(uint4*)&su[r * 36 + c * 4]       = qh4[gb + r * 8 + c];
            *(uint4*)&su[ARQ + r * 36 + c * 4] = ql4[gb + r * 8 + c];
        }
    }

    const int sr = t >> 3, scc = t & 7;
    {
        size_t kb = ((size_t)b * Sn + jt0 * 64) * 8;
#pragma unroll
        for (int i = 0; i < 2; i++) {
            int r = sr + i * 32;
            uint32_t dst = sbase + (OFF_ST0 + r * 36 + scc * 4) * 4;
            CPA16(dst,               (const char*)((const uint4*)g_kh + kb + r * 8 + scc));
            CPA16(dst + AR64 * 4,    (const char*)((const uint4*)g_kl + kb + r * 8 + scc));
            size_t vb = (size_t)(b * Hn + r) * 256 + jt0 * 8 + scc;
            CPA16(dst + 2*AR64 * 4,  (const char*)((const uint4*)g_vth + vb));
            CPA16(dst + 3*AR64 * 4,  (const char*)((const uint4*)g_vtl + vb));
        }
        CPC();
    }

    float m0r = -1e30f, m1r = -1e30f, l0r = 0.0f, l1r = 0.0f;
    float O[8][4];
#pragma unroll
    for (int j = 0; j < 8; j++)
#pragma unroll
        for (int i = 0; i < 4; i++) O[j][i] = 0.0f;

    for (int jt = jt0; jt < jt1; jt++) {
        const int buf = (jt - jt0) & 1;
        if (jt + 1 < jt1) {
            size_t kb = ((size_t)b * Sn + (jt + 1) * 64) * 8;
            uint32_t stb = OFF_ST0 + (buf ^ 1) * STG_SZ;
#pragma unroll
            for (int i = 0; i < 2; i++) {
                int r = sr + i * 32;
                uint32_t dst = sbase + (stb + r * 36 + scc * 4) * 4;
                CPA16(dst,              (const char*)((const uint4*)g_kh + kb + r * 8 + scc));
                CPA16(dst + AR64 * 4,   (const char*)((const uint4*)g_kl + kb + r * 8 + scc));
                size_t vb = (size_t)(b * Hn + r) * 256 + (jt + 1) * 8 + scc;
                CPA16(dst + 2*AR64 * 4, (const char*)((const uint4*)g_vth + vb));
                CPA16(dst + 3*AR64 * 4, (const char*)((const uint4*)g_vtl + vb));
            }
            CPC();
            CPW1();
        } else {
            CPW0();
        }
        __syncthreads();

        const uint32_t stB = sbase + (OFF_ST0 + buf * STG_SZ) * 4;

        uint32_t aQh[4][4], aQl[4][4];
#pragma unroll
        for (int ks = 0; ks < 4; ks++) {
            uint32_t ad = sbase + arow * 144 + ks * 32 + acolB;
            LDMX4(aQh[ks], ad);
            LDMX4(aQl[ks], ad + ARQ * 4);
        }

        float S[8][4];
#pragma unroll
        for (int j = 0; j < 8; j++)
#pragma unroll
            for (int i = 0; i < 4; i++) S[j][i] = 0.0f;
#pragma unroll
        for (int j = 0; j < 8; j++) {
            uint32_t adh = stB + ((j * 8 + brow) * 36) * 4 + bcolB;
            uint32_t adl = adh + AR64 * 4;
            uint32_t kh[4], kl[4], kh2[4], kl2[4];
            LDMX4(kh, adh);
            LDMX4(kl, adl);
            LDMX4(kh2, adh + 64);
            LDMX4(kl2, adl + 64);
            mma16816(S[j], aQh[0], kh[0], kh[1]);
            mma16816(S[j], aQl[0], kh[0], kh[1]);
            mma16816(S[j], aQh[0], kl[0], kl[1]);
            mma16816(S[j], aQh[1], kh[2], kh[3]);
            mma16816(S[j], aQl[1], kh[2], kh[3]);
            mma16816(S[j], aQh[1], kl[2], kl[3]);
            mma16816(S[j], aQh[2], kh2[0], kh2[1]);
            mma16816(S[j], aQl[2], kh2[0], kh2[1]);
            mma16816(S[j], aQh[2], kl2[0], kl2[1]);
            mma16816(S[j], aQh[3], kh2[2], kh2[3]);
            mma16816(S[j], aQl[3], kh2[2], kh2[3]);
            mma16816(S[j], aQh[3], kl2[2], kl2[3]);
        }

        if (jt >= 2 * qt) {
            int qg0 = qt * 128 + qrow, qg1 = qg0 + 8;
            int kbse = jt * 64;
#pragma unroll
            for (int j = 0; j < 8; j++) {
                int kc = kbse + j * 8 + 2 * tt;
                if (kc     > qg0) S[j][0] = -1e30f;
                if (kc + 1 > qg0) S[j][1] = -1e30f;
                if (kc     > qg1) S[j][2] = -1e30f;
                if (kc + 1 > qg1) S[j][3] = -1e30f;
            }
        }

        float mx0 = -1e30f, mx1 = -1e30f;
#pragma unroll
        for (int j = 0; j < 8; j++) {
            mx0 = fmaxf(mx0, fmaxf(S[j][0], S[j][1]));
            mx1 = fmaxf(mx1, fmaxf(S[j][2], S[j][3]));
        }
        mx0 = fmaxf(mx0, __shfl_xor_sync(0xffffffff, mx0, 1));
        mx0 = fmaxf(mx0, __shfl_xor_sync(0xffffffff, mx0, 2));
        mx1 = fmaxf(mx1, __shfl_xor_sync(0xffffffff, mx1, 1));
        mx1 = fmaxf(mx1, __shfl_xor_sync(0xffffffff, mx1, 2));
        float mn0 = fmaxf(m0r, mx0), mn1 = fmaxf(m1r, mx1);
        float al0 = fexp2((m0r - mn0) * C2), al1 = fexp2((m1r - mn1) * C2);
        l0r *= al0; l1r *= al1;
#pragma unroll
        for (int j = 0; j < 8; j++) {
            O[j][0] *= al0; O[j][1] *= al0; O[j][2] *= al1; O[j][3] *= al1;
        }

        uint32_t ph[4][4], pl[4][4];
        float s0 = 0.0f, s1 = 0.0f;
#pragma unroll
        for (int j = 0; j < 8; j++) {
            float p0 = fexp2((S[j][0] - mn0) * C2);
            float p1 = fexp2((S[j][1] - mn0) * C2);
            float p2 = fexp2((S[j][2] - mn1) * C2);
            float p3 = fexp2((S[j][3] - mn1) * C2);
            s0 += p0 + p1; s1 += p2 + p3;
            uint32_t h01 = pack2bf(p0, p1);
            uint32_t l01 = pack2bf(p0 - lowf(h01), p1 - highf(h01));
            uint32_t h23 = pack2bf(p2, p3);
            uint32_t l23 = pack2bf(p2 - lowf(h23), p3 - highf(h23));
            int s = j >> 1;
            if (!(j & 1)) { ph[s][0] = h01; ph[s][1] = h23; pl[s][0] = l01; pl[s][1] = l23; }
            else          { ph[s][2] = h01; ph[s][3] = h23; pl[s][2] = l01; pl[s][3] = l23; }
        }
        s0 += __shfl_xor_sync(0xffffffff, s0, 1);
        s0 += __shfl_xor_sync(0xffffffff, s0, 2);
        s1 += __shfl_xor_sync(0xffffffff, s1, 1);
        s1 += __shfl_xor_sync(0xffffffff, s1, 2);
        l0r += s0; l1r += s1;
        m0r = mn0; m1r = mn1;

#pragma unroll
        for (int j = 0; j < 8; j++) {
            uint32_t adh = stB + (2*AR64 + (j * 8 + brow) * 36) * 4 + bcolB;
            uint32_t adl = adh + AR64 * 4;
            uint32_t vh[4], vl[4], vh2[4], vl2[4];
            LDMX4(vh, adh);
            LDMX4(vl, adl);
            LDMX4(vh2, adh + 64);
            LDMX4(vl2, adl + 64);
            mma16816(O[j], ph[0], vh[0], vh[1]);
            mma16816(O[j], pl[0], vh[0], vh[1]);
            mma16816(O[j], ph[0], vl[0], vl[1]);
            mma16816(O[j], ph[1], vh[2], vh[3]);
            mma16816(O[j], pl[1], vh[2], vh[3]);
            mma16816(O[j], ph[1], vl[2], vl[3]);
            mma16816(O[j], ph[2], vh2[0], vh2[1]);
            mma16816(O[j], pl[2], vh2[0], vh2[1]);
            mma16816(O[j], ph[2], vl2[0], vl2[1]);
            mma16816(O[j], ph[3], vh2[2], vh2[3]);
            mma16816(O[j], pl[3], vh2[2], vh2[3]);
            mma16816(O[j], ph[3], vl2[2], vl2[3]);
        }
        __syncthreads();
    }

    const int slot = ((b * QT_N) + qt) * MAXC + chunk;
    float* po = g_po + (size_t)slot * 128 * 64;
#pragma unroll
    for (int j = 0; j < 8; j++) {
        *(float2*)&po[qrow * 64 + j * 8 + 2 * tt]       = make_float2(O[j][0], O[j][1]);
        *(float2*)&po[(qrow + 8) * 64 + j * 8 + 2 * tt] = make_float2(O[j][2], O[j][3]);
    }
    if (tt == 0) {
        g_pm[slot * 128 + qrow]     = m0r * 0.125f;
        g_pm[slot * 128 + qrow + 8] = m1r * 0.125f;
        g_pl[slot * 128 + qrow]     = l0r;
        g_pl[slot * 128 + qrow + 8] = l1r;
    }
}

// ------------------- combine (round-14, passing) -------------------
__global__ __launch_bounds__(256) void attn_combine_kernel(float* __restrict__ y)
{
    const int qt = blockIdx.x >> 2, quarter = blockIdx.x & 3, b = blockIdx.y;
    const int nc = min((2 * qt + 2 + CHUNK - 1) / CHUNK, MAXC);
    const int t = threadIdx.x;
    const int r = quarter * 32 + (t >> 3), c0 = (t & 7) * 8;
    const int base = ((b * QT_N) + qt) * MAXC;

    float M = -1e30f;
#pragma unroll
    for (int c = 0; c < MAXC; c++)
        if (c < nc) M = fmaxf(M, g_pm[(base + c) * 128 + r]);
    float wgt[MAXC];
    float L = 0.0f;
#pragma unroll
    for (int c = 0; c < MAXC; c++)
        if (c < nc) {
            wgt[c] = __expf(g_pm[(base + c) * 128 + r] - M);
            L += g_pl[(base + c) * 128 + r] * wgt[c];
        }
    const float inv = 1.0f / L;

    float acc[8];
#pragma unroll
    for (int k = 0; k < 8; k++) acc[k] = 0.0f;
    for (int c = 0; c < nc; c++) {
        const float* po = g_po + (size_t)(base + c) * 128 * 64 + r * 64 + c0;
        const float wc = wgt[c];
#pragma unroll
        for (int v = 0; v < 2; v++) {
            float4 p4 = *(const float4*)(po + v * 4);
            acc[v*4+0] = fmaf(p4.x, wc, acc[v*4+0]);
            acc[v*4+1] = fmaf(p4.y, wc, acc[v*4+1]);
            acc[v*4+2] = fmaf(p4.z, wc, acc[v*4+2]);
            acc[v*4+3] = fmaf(p4.w, wc, acc[v*4+3]);
        }
    }
    float* Y = y + ((size_t)b * Sn + qt * 128 + r) * Hn + c0;
#pragma unroll
    for (int v = 0; v < 2; v++) {
        *(float4*)(Y + v * 4) = make_float4(acc[v*4+0]*inv, acc[v*4+1]*inv,
                                            acc[v*4+2]*inv, acc[v*4+3]*inv);
    }
}

extern "C" void kernel_launch(void* const* d_in, const int* in_sizes, int n_in,
                              void* d_out, int out_size)
{
    const float* x  = (const float*)d_in[0];
    const float* wq = (const float*)d_in[1];
    const float* bq = (const float*)d_in[2];
    const float* wk = (const float*)d_in[3];
    const float* bk = (const float*)d_in[4];
    const float* wv = (const float*)d_in[5];
    const float* bv = (const float*)d_in[6];
    float* y = (float*)d_out;

    conv_w_kernel<<<(3 * Hn * En + 255) / 256, 256>>>(wq, wk, wv);

    cudaFuncSetAttribute(qkv_mma_kernel, cudaFuncAttributeMaxDynamicSharedMemorySize, QKV_SMEM);
    qkv_mma_kernel<<<Mn / 64, 256, QKV_SMEM>>>(x, bq, bk, bv);

    cudaFuncSetAttribute(attn_partial_kernel, cudaFuncAttributeMaxDynamicSharedMemorySize, ATT_SMEM);
    attn_partial_kernel<<<dim3(MAXC, QT_N, Bn), 256, ATT_SMEM>>>();

    attn_combine_kernel<<<dim3(4 * QT_N, Bn), 256>>>(y);
}